// round 9
// baseline (speedup 1.0000x reference)
#include <cuda_runtime.h>
#include <cstdint>

#define Dm 32
#define Hm 64
#define NMAX 50000
#define BMAX 16
#define TEB 128
#define SEIN 132
#define SXT 132
#define SMEM_EDGE_BYTES (64 * 128 * 4)      // sHT [64][128] dominates; sEinT [32][132] aliases
#define SMEM_NODE_BYTES (64 * SXT * 4)      // sIn [64][132]; sHT [64][128] aliases

// ---------------- scratch ----------------------------------------------------
__device__ __align__(16) float g_A  [NMAX * Hm];   // A' = x@W1a + hU[batch]
__device__ __align__(16) float g_Bp [NMAX * Hm];   // B  = x@W1b
__device__ __align__(16) float g_agg[NMAX * Dm];
__device__ __align__(16) float g_hU [BMAX * Hm];
__device__ __align__(16) float g_hUn[BMAX * Hm];
__device__ float g_deg [NMAX];
__device__ float g_rdeg[NMAX];

// ---------------- packed f32x2 helpers ---------------------------------------
static __device__ __forceinline__ uint64_t ffma2(uint64_t a, uint64_t b, uint64_t c) {
    uint64_t d; asm("fma.rn.f32x2 %0, %1, %2, %3;" : "=l"(d) : "l"(a), "l"(b), "l"(c));
    return d;
}
static __device__ __forceinline__ uint64_t pack2(float lo, float hi) {
    uint64_t r; asm("mov.b64 %0, {%1, %2};" : "=l"(r) : "f"(lo), "f"(hi));
    return r;
}
static __device__ __forceinline__ float2 unpack2(uint64_t v) {
    float lo, hi; asm("mov.b64 {%0, %1}, %2;" : "=f"(lo), "=f"(hi) : "l"(v));
    float2 f; f.x = lo; f.y = hi; return f;
}
static __device__ __forceinline__ void red_add_v4(float* p, float a, float b, float c, float d) {
    asm volatile("red.global.add.v4.f32 [%0], {%1, %2, %3, %4};"
                 :: "l"(p), "f"(a), "f"(b), "f"(c), "f"(d) : "memory");
}

// ---------------- launch 0: BN for x and u (+ zero deg) ----------------------
__global__ void k_bn_xu(const float4* __restrict__ nf, const float4* __restrict__ gf,
                        float4* __restrict__ x, float4* __restrict__ u,
                        const float* __restrict__ ngam, const float* __restrict__ nbet,
                        const float* __restrict__ ggam, const float* __restrict__ gbet,
                        int N, int B, int XB) {
    const float r = rsqrtf(1.0f + 1e-5f);
    int bid = blockIdx.x, t = threadIdx.x;
    const float4* in; float4* out; const float* gm; const float* bt; int i4, lim;
    if (bid < XB) { i4 = bid * 256 + t; lim = N * 8; in = nf; out = x; gm = ngam; bt = nbet;
                    if (i4 < N) g_deg[i4] = 0.0f; }
    else          { i4 = t;             lim = B * 8; in = gf; out = u; gm = ggam; bt = gbet; }
    if (i4 >= lim) return;
    float4 v = in[i4];
    int c = (i4 * 4) & (Dm - 1);
    v.x = v.x * (gm[c + 0] * r) + bt[c + 0];
    v.y = v.y * (gm[c + 1] * r) + bt[c + 1];
    v.z = v.z * (gm[c + 2] * r) + bt[c + 2];
    v.w = v.w * (gm[c + 3] * r) + bt[c + 3];
    out[i4] = v;
}

// ---------------- hU/hUn body -------------------------------------------------
static __device__ __forceinline__ void hu_body(
    const float* __restrict__ u,
    const float* __restrict__ eW1, const float* __restrict__ eb1,
    const float* __restrict__ nW1, const float* __restrict__ nb1,
    const float* __restrict__ ebet, int B, int j)
{
    float c = 0.f;
    if (ebet) {            // layer 0: BN shift of e folded through W1c
#pragma unroll 4
        for (int k = 0; k < Dm; k++) c += ebet[k] * eW1[(2 * Dm + k) * Hm + j];
    }
    for (int b = 0; b < B; b++) {
        float hu = eb1[j] + c, hun = nb1[j];
#pragma unroll 4
        for (int k = 0; k < Dm; k++) {
            float uv = u[b * Dm + k];
            hu  += uv * eW1[(3 * Dm + k) * Hm + j];
            hun += uv * nW1[(2 * Dm + k) * Hm + j];
        }
        g_hU [b * Hm + j] = hu;
        g_hUn[b * Hm + j] = hun;
    }
}

// ---------------- launch 1: deg count + layer-0 hU ----------------------------
__global__ void k_deg_hu(const int* __restrict__ dst, const float* __restrict__ u,
                         const float* __restrict__ eW1, const float* __restrict__ eb1,
                         const float* __restrict__ nW1, const float* __restrict__ nb1,
                         const float* __restrict__ ebet, int E, int B) {
    if (blockIdx.x == gridDim.x - 1) {
        if (threadIdx.x < Hm) hu_body(u, eW1, eb1, nW1, nb1, ebet, B, threadIdx.x);
        return;
    }
    int i = blockIdx.x * blockDim.x + threadIdx.x;
    if (i < E) atomicAdd(&g_deg[dst[i]], 1.0f);
}

// layers 1,2: standalone hU
__global__ void k_hu(const float* __restrict__ u,
                     const float* __restrict__ eW1, const float* __restrict__ eb1,
                     const float* __restrict__ nW1, const float* __restrict__ nb1, int B) {
    if (threadIdx.x < Hm) hu_body(u, eW1, eb1, nW1, nb1, nullptr, B, threadIdx.x);
}

// ---------------- per-layer: A'/B precompute (tiled GEMM) + rdeg + zero agg ---
// 128 threads, 128-node tiles.
__global__ void __launch_bounds__(128, 4) k_pre(const float* __restrict__ x,
                                                const int* __restrict__ batch,
                                                const float* __restrict__ eW1, int N) {
    __shared__ __align__(16) float sX[32 * SXT];
    __shared__ int sBt[TEB];
    int t = threadIdx.x;
    int n0 = blockIdx.x * TEB;
    sBt[t] = batch[min(n0 + t, N - 1)];
    if (n0 + t < N) g_rdeg[n0 + t] = 1.0f / fmaxf(g_deg[n0 + t], 1.0f);
    {   // zero this block's agg region
        float4 z = make_float4(0.f, 0.f, 0.f, 0.f);
        float4* pz = (float4*)(g_agg + (size_t)n0 * Dm);
        int lim4 = min(TEB, N - n0) * 8;
        for (int i = t; i < lim4; i += TEB) pz[i] = z;
    }
    {   // stage x^T, quad swizzle
        int l8 = t & 7, g8 = t >> 3, k0 = l8 * 4;   // g8 in [0,16)
#pragma unroll 2
        for (int p = 0; p < 8; p++) {
            int nL = p * 16 + g8;
            int ngl = min(n0 + nL, N - 1);
            float4 v = __ldg((const float4*)(x + (size_t)ngl * Dm) + l8);
            int col = (((nL >> 2) ^ l8) << 2) + (nL & 3);
            sX[(k0 + 0) * SXT + col] = v.x;
            sX[(k0 + 1) * SXT + col] = v.y;
            sX[(k0 + 2) * SXT + col] = v.z;
            sX[(k0 + 3) * SXT + col] = v.w;
        }
    }
    __syncthreads();

    int jb = t & 7, nbk = t >> 3;       // nbk in [0,16)
    uint64_t acc[8][4];
#pragma unroll
    for (int g = 0; g < 2; g++) {       // g=0: A' (rows 0..31, hU bias); g=1: B (rows 32..63)
        const float* W = eW1 + g * Dm * Hm;
        float* O = g ? g_Bp : g_A;
#pragma unroll
        for (int i = 0; i < 8; i++) {
            if (g == 0) {
                int bb = sBt[nbk * 8 + i];
                const ulonglong2* pb = (const ulonglong2*)(g_hU + bb * Hm + jb * 8);
                ulonglong2 b0 = __ldg(pb), b1 = __ldg(pb + 1);
                acc[i][0] = b0.x; acc[i][1] = b0.y; acc[i][2] = b1.x; acc[i][3] = b1.y;
            } else {
                acc[i][0] = acc[i][1] = acc[i][2] = acc[i][3] = 0ull;
            }
        }
#pragma unroll 4
        for (int k = 0; k < Dm; k++) {
            int sw = k >> 2;
            const float4* pe = (const float4*)(sX + k * SXT);
            float4 ea = pe[(nbk * 2) ^ sw];
            float4 eb = pe[(nbk * 2 + 1) ^ sw];
            ulonglong2 wA = __ldg((const ulonglong2*)(W + k * Hm + jb * 8));
            ulonglong2 wB = __ldg((const ulonglong2*)(W + k * Hm + jb * 8 + 4));
            float ev[8] = {ea.x, ea.y, ea.z, ea.w, eb.x, eb.y, eb.z, eb.w};
#pragma unroll
            for (int i = 0; i < 8; i++) {
                uint64_t ed = pack2(ev[i], ev[i]);
                acc[i][0] = ffma2(ed, wA.x, acc[i][0]);
                acc[i][1] = ffma2(ed, wA.y, acc[i][1]);
                acc[i][2] = ffma2(ed, wB.x, acc[i][2]);
                acc[i][3] = ffma2(ed, wB.y, acc[i][3]);
            }
        }
#pragma unroll
        for (int i = 0; i < 8; i++) {
            int n = n0 + nbk * 8 + i;
            if (n < N) {
                float2 a0 = unpack2(acc[i][0]), a1 = unpack2(acc[i][1]);
                float2 a2 = unpack2(acc[i][2]), a3 = unpack2(acc[i][3]);
                *(float4*)(O + (size_t)n * Hm + jb * 8)     = make_float4(a0.x, a0.y, a1.x, a1.y);
                *(float4*)(O + (size_t)n * Hm + jb * 8 + 4) = make_float4(a2.x, a2.y, a3.x, a3.y);
            }
        }
    }
}

// ---------------- per-layer: edge MLP — persistent 128-thread tiles ----------
__global__ void __launch_bounds__(128, 4) k_edge(
    const int* __restrict__ src, const int* __restrict__ dst,
    const float* __restrict__ ein, float* __restrict__ eout,
    const float* __restrict__ W1c, const float* __restrict__ W2,
    const float* __restrict__ b2, const float* __restrict__ escale,
    int E, int nTiles)
{
    extern __shared__ float smem[];
    float* sEinT = smem;                  // [32][132], alive through GEMM1
    float* sHT   = smem;                  // [64][128] overlay
    __shared__ int sS[TEB], sD[TEB];
    __shared__ float sSc[Dm];
    int t = threadIdx.x;
    if (t < Dm) sSc[t] = escale ? escale[t] * rsqrtf(1.0f + 1e-5f) : 1.0f;
    int jb = t & 7, ebk = t >> 3;         // ebk in [0,16)
    int l8 = t & 7, g8 = t >> 3;

    for (int tile = blockIdx.x; tile < nTiles; tile += gridDim.x) {
        int e0 = tile * TEB;
        __syncthreads();                  // prev tile's sHT/sD reads done
        int ei = min(e0 + t, E - 1);
        sS[t] = src[ei]; sD[t] = dst[ei];
        __syncthreads();                  // sS/sD (and first-iter sSc) visible

        // ---- stage Ein transposed, quad swizzle, BN scale fold ----
        {
            int k0 = l8 * 4;
            float s0 = sSc[k0], s1 = sSc[k0 + 1], s2 = sSc[k0 + 2], s3 = sSc[k0 + 3];
#pragma unroll 2
            for (int p = 0; p < 8; p++) {
                int eL = p * 16 + g8;
                int eg = min(e0 + eL, E - 1);
                float4 v = __ldg((const float4*)(ein + (size_t)eg * Dm) + l8);
                int col = (((eL >> 2) ^ l8) << 2) + (eL & 3);
                sEinT[(k0 + 0) * SEIN + col] = v.x * s0;
                sEinT[(k0 + 1) * SEIN + col] = v.y * s1;
                sEinT[(k0 + 2) * SEIN + col] = v.z * s2;
                sEinT[(k0 + 3) * SEIN + col] = v.w * s3;
            }
        }
        // ---- direct bias init: acc = A'[src] + B[dst] ----
        uint64_t acc[8][4];
#pragma unroll
        for (int i = 0; i < 8; i++) {
            int eL = ebk * 8 + i;
            const float4* pa = (const float4*)(g_A  + (size_t)sS[eL] * Hm + jb * 8);
            const float4* pb = (const float4*)(g_Bp + (size_t)sD[eL] * Hm + jb * 8);
            float4 a0 = __ldg(pa), a1 = __ldg(pa + 1);
            float4 b0 = __ldg(pb), b1 = __ldg(pb + 1);
            acc[i][0] = pack2(a0.x + b0.x, a0.y + b0.y);
            acc[i][1] = pack2(a0.z + b0.z, a0.w + b0.w);
            acc[i][2] = pack2(a1.x + b1.x, a1.y + b1.y);
            acc[i][3] = pack2(a1.z + b1.z, a1.w + b1.w);
        }
        __syncthreads();                  // sEinT staged

        // ---- GEMM1: H[128x64] = EinT^T @ W1c + bias ----
#pragma unroll 4
        for (int k = 0; k < Dm; k++) {
            int sw = k >> 2;
            const float4* pe = (const float4*)(sEinT + k * SEIN);
            float4 ea = pe[(ebk * 2) ^ sw];
            float4 eb = pe[(ebk * 2 + 1) ^ sw];
            ulonglong2 wA = __ldg((const ulonglong2*)(W1c + k * Hm + jb * 8));
            ulonglong2 wB = __ldg((const ulonglong2*)(W1c + k * Hm + jb * 8 + 4));
            float ev[8] = {ea.x, ea.y, ea.z, ea.w, eb.x, eb.y, eb.z, eb.w};
#pragma unroll
            for (int i = 0; i < 8; i++) {
                uint64_t ed = pack2(ev[i], ev[i]);
                acc[i][0] = ffma2(ed, wA.x, acc[i][0]);
                acc[i][1] = ffma2(ed, wA.y, acc[i][1]);
                acc[i][2] = ffma2(ed, wB.x, acc[i][2]);
                acc[i][3] = ffma2(ed, wB.y, acc[i][3]);
            }
        }
        __syncthreads();                  // sEinT dead; overlay sHT

        // ---- relu + store H^T [64][128], quad swizzle q ^ jb ----
#pragma unroll
        for (int jj = 0; jj < 8; jj++) {
            int j = jb * 8 + jj;
            float f[8];
#pragma unroll
            for (int i = 0; i < 8; i++) {
                float2 v = unpack2(acc[i][jj >> 1]);
                f[i] = fmaxf((jj & 1) ? v.y : v.x, 0.f);
            }
            *(float4*)(sHT + j * 128 + (((ebk * 2)     ^ jb) << 2)) = make_float4(f[0], f[1], f[2], f[3]);
            *(float4*)(sHT + j * 128 + (((ebk * 2 + 1) ^ jb) << 2)) = make_float4(f[4], f[5], f[6], f[7]);
        }
        __syncthreads();

        // ---- GEMM2: OUT[128x32] = relu(H) @ W2 + b2 ----
        uint64_t out[8][2];
        {
            ulonglong2 bb = __ldg((const ulonglong2*)(b2 + jb * 4));
#pragma unroll
            for (int i = 0; i < 8; i++) { out[i][0] = bb.x; out[i][1] = bb.y; }
        }
#pragma unroll 4
        for (int k = 0; k < Hm; k++) {
            int sw = (k >> 3) & 7;
            const float4* ph = (const float4*)(sHT + k * 128);
            float4 h0 = ph[(ebk * 2) ^ sw];
            float4 h1 = ph[(ebk * 2 + 1) ^ sw];
            ulonglong2 w = __ldg((const ulonglong2*)(W2 + k * Dm + jb * 4));
            float hv[8] = {h0.x, h0.y, h0.z, h0.w, h1.x, h1.y, h1.z, h1.w};
#pragma unroll
            for (int i = 0; i < 8; i++) {
                uint64_t hd = pack2(hv[i], hv[i]);
                out[i][0] = ffma2(hd, w.x, out[i][0]);
                out[i][1] = ffma2(hd, w.y, out[i][1]);
            }
        }
        // ---- epilogue: write e + fused RED into agg ----
#pragma unroll
        for (int i = 0; i < 8; i++) {
            int eL = ebk * 8 + i, eg = e0 + eL;
            if (eg < E) {
                float2 a = unpack2(out[i][0]); float2 b = unpack2(out[i][1]);
                *(float4*)(eout + (size_t)eg * Dm + jb * 4) = make_float4(a.x, a.y, b.x, b.y);
                red_add_v4(g_agg + (size_t)sD[eL] * Dm + jb * 4, a.x, a.y, b.x, b.y);
            }
        }
    }
}

// ---------------- per-layer: node MLP — 128-thread tiles ---------------------
__global__ void __launch_bounds__(128, 4) k_node(
    float* __restrict__ x, const int* __restrict__ batch,
    const float* __restrict__ W1, const float* __restrict__ W2, const float* __restrict__ b2,
    int N)
{
    extern __shared__ float smem[];
    float* sIn = smem;     // [64][132]: rows 0..31 = x^T, rows 32..63 = (agg*rd)^T
    float* sHT = smem;     // overlay after GEMM1: [64][128]
    __shared__ int sBt[TEB];
    int t = threadIdx.x;
    int n0 = blockIdx.x * TEB;
    sBt[t] = batch[min(n0 + t, N - 1)];
    {
        int l8 = t & 7, g8 = t >> 3, k0 = l8 * 4;
#pragma unroll 2
        for (int p = 0; p < 8; p++) {
            int nL = p * 16 + g8;
            int ngl = min(n0 + nL, N - 1);
            float4 vx = __ldg((const float4*)(x + (size_t)ngl * Dm) + l8);
            float rd = g_rdeg[ngl];
            float4 va = __ldg((const float4*)(g_agg + (size_t)ngl * Dm) + l8);
            int col = (((nL >> 2) ^ l8) << 2) + (nL & 3);
            sIn[(k0 + 0) * SXT + col] = vx.x;
            sIn[(k0 + 1) * SXT + col] = vx.y;
            sIn[(k0 + 2) * SXT + col] = vx.z;
            sIn[(k0 + 3) * SXT + col] = vx.w;
            sIn[(Dm + k0 + 0) * SXT + col] = va.x * rd;
            sIn[(Dm + k0 + 1) * SXT + col] = va.y * rd;
            sIn[(Dm + k0 + 2) * SXT + col] = va.z * rd;
            sIn[(Dm + k0 + 3) * SXT + col] = va.w * rd;
        }
    }
    __syncthreads();

    // ---- GEMM1: H[128x64] = In^T @ W1(rows 0..63) + hUn[batch] ----
    int jb = t & 7, nbk = t >> 3;
    uint64_t acc[8][4];
#pragma unroll
    for (int i = 0; i < 8; i++) {
        int bb = sBt[nbk * 8 + i];
        const ulonglong2* pb = (const ulonglong2*)(g_hUn + bb * Hm + jb * 8);
        ulonglong2 b0 = __ldg(pb), b1 = __ldg(pb + 1);
        acc[i][0] = b0.x; acc[i][1] = b0.y; acc[i][2] = b1.x; acc[i][3] = b1.y;
    }
#pragma unroll 4
    for (int k = 0; k < 2 * Dm; k++) {
        int sw = (k >> 2) & 7;
        const float4* pe = (const float4*)(sIn + k * SXT);
        float4 ea = pe[(nbk * 2) ^ sw];
        float4 eb = pe[(nbk * 2 + 1) ^ sw];
        ulonglong2 wA = __ldg((const ulonglong2*)(W1 + k * Hm + jb * 8));
        ulonglong2 wB = __ldg((const ulonglong2*)(W1 + k * Hm + jb * 8 + 4));
        float ev[8] = {ea.x, ea.y, ea.z, ea.w, eb.x, eb.y, eb.z, eb.w};
#pragma unroll
        for (int i = 0; i < 8; i++) {
            uint64_t ed = pack2(ev[i], ev[i]);
            acc[i][0] = ffma2(ed, wA.x, acc[i][0]);
            acc[i][1] = ffma2(ed, wA.y, acc[i][1]);
            acc[i][2] = ffma2(ed, wB.x, acc[i][2]);
            acc[i][3] = ffma2(ed, wB.y, acc[i][3]);
        }
    }
    __syncthreads();   // all reads of sIn complete before HT overlay

#pragma unroll
    for (int jj = 0; jj < 8; jj++) {
        int j = jb * 8 + jj;
        float f[8];
#pragma unroll
        for (int i = 0; i < 8; i++) {
            float2 v = unpack2(acc[i][jj >> 1]);
            f[i] = fmaxf((jj & 1) ? v.y : v.x, 0.f);
        }
        *(float4*)(sHT + j * 128 + (((nbk * 2)     ^ jb) << 2)) = make_float4(f[0], f[1], f[2], f[3]);
        *(float4*)(sHT + j * 128 + (((nbk * 2 + 1) ^ jb) << 2)) = make_float4(f[4], f[5], f[6], f[7]);
    }
    __syncthreads();

    // ---- GEMM2: OUT[128x32] = relu(H) @ W2 + b2 ----
    uint64_t out[8][2];
    {
        ulonglong2 bb = __ldg((const ulonglong2*)(b2 + jb * 4));
#pragma unroll
        for (int i = 0; i < 8; i++) { out[i][0] = bb.x; out[i][1] = bb.y; }
    }
#pragma unroll 4
    for (int k = 0; k < Hm; k++) {
        int sw = (k >> 3) & 7;
        const float4* ph = (const float4*)(sHT + k * 128);
        float4 h0 = ph[(nbk * 2) ^ sw];
        float4 h1 = ph[(nbk * 2 + 1) ^ sw];
        ulonglong2 w = __ldg((const ulonglong2*)(W2 + k * Dm + jb * 4));
        float hv[8] = {h0.x, h0.y, h0.z, h0.w, h1.x, h1.y, h1.z, h1.w};
#pragma unroll
        for (int i = 0; i < 8; i++) {
            uint64_t hd = pack2(hv[i], hv[i]);
            out[i][0] = ffma2(hd, w.x, out[i][0]);
            out[i][1] = ffma2(hd, w.y, out[i][1]);
        }
    }
#pragma unroll
    for (int i = 0; i < 8; i++) {
        int n = n0 + nbk * 8 + i;
        if (n < N) {
            float2 a = unpack2(out[i][0]); float2 b = unpack2(out[i][1]);
            *(float4*)(x + (size_t)n * Dm + jb * 4) = make_float4(a.x, a.y, b.x, b.y);
        }
    }
}

// ---------------- per-layer: global MLP (sorted-batch segment reduce) --------
static __device__ __forceinline__ int lowerb(const int* __restrict__ a, int n, int v) {
    int lo = 0, hi = n;
    while (lo < hi) { int m = (lo + hi) >> 1; if (a[m] < v) lo = m + 1; else hi = m; }
    return lo;
}
__global__ void k_glob(float* __restrict__ u, const float* __restrict__ x,
                       const int* __restrict__ batch,
                       const float* __restrict__ W1, const float* __restrict__ b1,
                       const float* __restrict__ W2, const float* __restrict__ b2, int N) {
    int b = blockIdx.x, t = threadIdx.x;       // 128 threads
    __shared__ int sLo, sHi;
    if (t == 0) { sLo = lowerb(batch, N, b); sHi = lowerb(batch, N, b + 1); }
    __syncthreads();
    int lo = sLo, hi = sHi;
    float cnt = fmaxf((float)(hi - lo), 1.0f);
    int c = t & 31, g = t >> 5;
    float acc = 0.f;
    for (int r = lo + g; r < hi; r += 4) acc += x[(size_t)r * Dm + c];
    __shared__ float sred[4][Dm];
    sred[g][c] = acc;
    __syncthreads();
    __shared__ float su[2 * Dm];
    __shared__ float sh[Hm];
    if (t < Dm) su[t] = u[b * Dm + t];
    else if (t < 2 * Dm) {
        int cc = t - Dm;
        su[t] = (sred[0][cc] + sred[1][cc] + sred[2][cc] + sred[3][cc]) / cnt;
    }
    __syncthreads();
    if (t < Hm) {
        float h = b1[t];
#pragma unroll 4
        for (int k = 0; k < 2 * Dm; k++) h += su[k] * W1[k * Hm + t];
        sh[t] = fmaxf(h, 0.f);
    }
    __syncthreads();
    if (t < Dm) {
        float o = b2[t];
#pragma unroll 4
        for (int k = 0; k < Hm; k++) o += sh[k] * W2[k * Dm + t];
        u[b * Dm + t] = o;
    }
}

// ---------------- launch -----------------------------------------------------
extern "C" void kernel_launch(void* const* d_in, const int* in_sizes, int n_in,
                              void* d_out, int out_size) {
    const float* node_feats = (const float*)d_in[0];
    const int*   edge_index = (const int*)  d_in[1];
    const float* edge_feats = (const float*)d_in[2];
    const float* glob_feats = (const float*)d_in[3];
    const int*   batch      = (const int*)  d_in[4];
    const float* ngam = (const float*)d_in[5];
    const float* nbet = (const float*)d_in[6];
    const float* egam = (const float*)d_in[7];
    const float* ebet = (const float*)d_in[8];
    const float* ggam = (const float*)d_in[9];
    const float* gbet = (const float*)d_in[10];
    const float* eW1 = (const float*)d_in[11];
    const float* eb1 = (const float*)d_in[12];
    const float* eW2 = (const float*)d_in[13];
    const float* eb2 = (const float*)d_in[14];
    const float* nW1 = (const float*)d_in[15];
    const float* nb1 = (const float*)d_in[16];
    const float* nW2 = (const float*)d_in[17];
    const float* nb2 = (const float*)d_in[18];
    const float* gW1 = (const float*)d_in[19];
    const float* gb1 = (const float*)d_in[20];
    const float* gW2 = (const float*)d_in[21];
    const float* gb2 = (const float*)d_in[22];

    const int N = in_sizes[0] / Dm;
    const int E = in_sizes[2] / Dm;
    const int B = in_sizes[3] / Dm;

    float* x = (float*)d_out;
    float* e = x + (size_t)N * Dm;
    float* u = e + (size_t)E * Dm;
    const int* src = edge_index;
    const int* dst = edge_index + E;

    const int TB = 256;
    int XB = (N * 8 + TB - 1) / TB;
    int gE = (E + TB - 1) / TB;
    int gN128 = (N + TEB - 1) / TEB;
    int nTiles = (E + TEB - 1) / TEB;
    int gEdge = nTiles < 592 ? nTiles : 592;   // 4 blocks/SM x 148 SMs

    // launch 0: BN(x,u) + zero deg
    k_bn_xu<<<XB + 1, TB>>>((const float4*)node_feats, (const float4*)glob_feats,
                            (float4*)x, (float4*)u, ngam, nbet, ggam, gbet, N, B, XB);
    // launch 1: deg count + layer-0 hU
    k_deg_hu<<<gE + 1, TB>>>(dst, u, eW1, eb1, nW1, nb1, ebet, E, B);

    for (int l = 0; l < 3; l++) {
        const float* eW1l = eW1 + (size_t)l * 4 * Dm * Hm;   // (128,64)
        const float* nW1l = nW1 + (size_t)l * 3 * Dm * Hm;   // (96,64)
        const float* gW1l = gW1 + (size_t)l * 2 * Dm * Hm;   // (64,64)
        if (l > 0)
            k_hu<<<1, Hm>>>(u, eW1l, eb1 + l * Hm, nW1l, nb1 + l * Hm, B);
        k_pre<<<gN128, TEB>>>(x, batch, eW1l, N);            // launch 2 (l=0)
        k_edge<<<gEdge, TEB, SMEM_EDGE_BYTES>>>(src, dst,    // launch 3 (l=0) — profiled
                           (l == 0) ? edge_feats : e, e,
                           eW1l + 2 * Dm * Hm,               // rows 64..95 (e part)
                           eW2 + (size_t)l * Hm * Dm, eb2 + l * Dm,
                           (l == 0) ? egam : (const float*)nullptr, E, nTiles);
        k_node<<<gN128, TEB, SMEM_NODE_BYTES>>>(x, batch, nW1l,
                           nW2 + (size_t)l * Hm * Dm, nb2 + l * Dm, N);
        k_glob<<<B, 128>>>(u, x, batch, gW1l, gb1 + l * Hm,
                           gW2 + (size_t)l * Hm * Dm, gb2 + l * Dm, N);
    }
}

// round 11
// speedup vs baseline: 1.0290x; 1.0290x over previous
#include <cuda_runtime.h>
#include <cstdint>

#define Dm 32
#define Hm 64
#define NMAX 50000
#define BMAX 16
#define TEB 128
#define SEIN 132
#define SXT 132
#define SMEM_EDGE_BYTES (64 * 128 * 4)      // sHT [64][128] dominates; sEinT [32][132] aliases
#define SMEM_NODE_BYTES (64 * SXT * 4)      // sIn [64][132]; sHT [64][128] aliases

// ---------------- scratch ----------------------------------------------------
__device__ __align__(16) float g_A  [NMAX * Hm];   // A' = x@W1a + hU[batch]
__device__ __align__(16) float g_Bp [NMAX * Hm];   // B  = x@W1b
__device__ __align__(16) float g_agg[NMAX * Dm];
__device__ __align__(16) float g_hU [BMAX * Hm];
__device__ __align__(16) float g_hUn[BMAX * Hm];
__device__ float g_deg [NMAX];
__device__ float g_rdeg[NMAX];

// ---------------- packed f32x2 helpers ---------------------------------------
static __device__ __forceinline__ uint64_t ffma2(uint64_t a, uint64_t b, uint64_t c) {
    uint64_t d; asm("fma.rn.f32x2 %0, %1, %2, %3;" : "=l"(d) : "l"(a), "l"(b), "l"(c));
    return d;
}
static __device__ __forceinline__ uint64_t pack2(float lo, float hi) {
    uint64_t r; asm("mov.b64 %0, {%1, %2};" : "=l"(r) : "f"(lo), "f"(hi));
    return r;
}
static __device__ __forceinline__ float2 unpack2(uint64_t v) {
    float lo, hi; asm("mov.b64 {%0, %1}, %2;" : "=f"(lo), "=f"(hi) : "l"(v));
    float2 f; f.x = lo; f.y = hi; return f;
}
static __device__ __forceinline__ void red_add_v4(float* p, float a, float b, float c, float d) {
    asm volatile("red.global.add.v4.f32 [%0], {%1, %2, %3, %4};"
                 :: "l"(p), "f"(a), "f"(b), "f"(c), "f"(d) : "memory");
}

// ---------------- launch 0: BN for x and u (+ zero deg) ----------------------
__global__ void k_bn_xu(const float4* __restrict__ nf, const float4* __restrict__ gf,
                        float4* __restrict__ x, float4* __restrict__ u,
                        const float* __restrict__ ngam, const float* __restrict__ nbet,
                        const float* __restrict__ ggam, const float* __restrict__ gbet,
                        int N, int B, int XB) {
    const float r = rsqrtf(1.0f + 1e-5f);
    int bid = blockIdx.x, t = threadIdx.x;
    const float4* in; float4* out; const float* gm; const float* bt; int i4, lim;
    if (bid < XB) { i4 = bid * 256 + t; lim = N * 8; in = nf; out = x; gm = ngam; bt = nbet;
                    if (i4 < N) g_deg[i4] = 0.0f; }
    else          { i4 = t;             lim = B * 8; in = gf; out = u; gm = ggam; bt = gbet; }
    if (i4 >= lim) return;
    float4 v = in[i4];
    int c = (i4 * 4) & (Dm - 1);
    v.x = v.x * (gm[c + 0] * r) + bt[c + 0];
    v.y = v.y * (gm[c + 1] * r) + bt[c + 1];
    v.z = v.z * (gm[c + 2] * r) + bt[c + 2];
    v.w = v.w * (gm[c + 3] * r) + bt[c + 3];
    out[i4] = v;
}

// ---------------- hU/hUn body -------------------------------------------------
static __device__ __forceinline__ void hu_body(
    const float* __restrict__ u,
    const float* __restrict__ eW1, const float* __restrict__ eb1,
    const float* __restrict__ nW1, const float* __restrict__ nb1,
    const float* __restrict__ ebet, int B, int j)
{
    float c = 0.f;
    if (ebet) {            // layer 0: BN shift of e folded through W1c
#pragma unroll 4
        for (int k = 0; k < Dm; k++) c += ebet[k] * eW1[(2 * Dm + k) * Hm + j];
    }
    for (int b = 0; b < B; b++) {
        float hu = eb1[j] + c, hun = nb1[j];
#pragma unroll 4
        for (int k = 0; k < Dm; k++) {
            float uv = u[b * Dm + k];
            hu  += uv * eW1[(3 * Dm + k) * Hm + j];
            hun += uv * nW1[(2 * Dm + k) * Hm + j];
        }
        g_hU [b * Hm + j] = hu;
        g_hUn[b * Hm + j] = hun;
    }
}

// ---------------- launch 1: deg count + layer-0 hU ----------------------------
__global__ void k_deg_hu(const int* __restrict__ dst, const float* __restrict__ u,
                         const float* __restrict__ eW1, const float* __restrict__ eb1,
                         const float* __restrict__ nW1, const float* __restrict__ nb1,
                         const float* __restrict__ ebet, int E, int B) {
    if (blockIdx.x == gridDim.x - 1) {
        if (threadIdx.x < Hm) hu_body(u, eW1, eb1, nW1, nb1, ebet, B, threadIdx.x);
        return;
    }
    int i = blockIdx.x * blockDim.x + threadIdx.x;
    if (i < E) atomicAdd(&g_deg[dst[i]], 1.0f);
}

// layers 1,2: standalone hU
__global__ void k_hu(const float* __restrict__ u,
                     const float* __restrict__ eW1, const float* __restrict__ eb1,
                     const float* __restrict__ nW1, const float* __restrict__ nb1, int B) {
    if (threadIdx.x < Hm) hu_body(u, eW1, eb1, nW1, nb1, nullptr, B, threadIdx.x);
}

// ---------------- per-layer: A'/B precompute (tiled GEMM) + rdeg + zero agg ---
// 128 threads, 128-node tiles.
__global__ void __launch_bounds__(128, 4) k_pre(const float* __restrict__ x,
                                                const int* __restrict__ batch,
                                                const float* __restrict__ eW1, int N) {
    __shared__ __align__(16) float sX[32 * SXT];
    __shared__ int sBt[TEB];
    int t = threadIdx.x;
    int n0 = blockIdx.x * TEB;
    sBt[t] = batch[min(n0 + t, N - 1)];
    if (n0 + t < N) g_rdeg[n0 + t] = 1.0f / fmaxf(g_deg[n0 + t], 1.0f);
    {   // zero this block's agg region
        float4 z = make_float4(0.f, 0.f, 0.f, 0.f);
        float4* pz = (float4*)(g_agg + (size_t)n0 * Dm);
        int lim4 = min(TEB, N - n0) * 8;
        for (int i = t; i < lim4; i += TEB) pz[i] = z;
    }
    {   // stage x^T, quad swizzle
        int l8 = t & 7, g8 = t >> 3, k0 = l8 * 4;   // g8 in [0,16)
#pragma unroll 2
        for (int p = 0; p < 8; p++) {
            int nL = p * 16 + g8;
            int ngl = min(n0 + nL, N - 1);
            float4 v = __ldg((const float4*)(x + (size_t)ngl * Dm) + l8);
            int col = (((nL >> 2) ^ l8) << 2) + (nL & 3);
            sX[(k0 + 0) * SXT + col] = v.x;
            sX[(k0 + 1) * SXT + col] = v.y;
            sX[(k0 + 2) * SXT + col] = v.z;
            sX[(k0 + 3) * SXT + col] = v.w;
        }
    }
    __syncthreads();

    int jb = t & 7, nbk = t >> 3;       // nbk in [0,16)
    uint64_t acc[8][4];
#pragma unroll
    for (int g = 0; g < 2; g++) {       // g=0: A' (rows 0..31, hU bias); g=1: B (rows 32..63)
        const float* W = eW1 + g * Dm * Hm;
        float* O = g ? g_Bp : g_A;
#pragma unroll
        for (int i = 0; i < 8; i++) {
            if (g == 0) {
                int bb = sBt[nbk * 8 + i];
                const ulonglong2* pb = (const ulonglong2*)(g_hU + bb * Hm + jb * 8);
                ulonglong2 b0 = __ldg(pb), b1 = __ldg(pb + 1);
                acc[i][0] = b0.x; acc[i][1] = b0.y; acc[i][2] = b1.x; acc[i][3] = b1.y;
            } else {
                acc[i][0] = acc[i][1] = acc[i][2] = acc[i][3] = 0ull;
            }
        }
#pragma unroll 4
        for (int k = 0; k < Dm; k++) {
            int sw = k >> 2;
            const float4* pe = (const float4*)(sX + k * SXT);
            float4 ea = pe[(nbk * 2) ^ sw];
            float4 eb = pe[(nbk * 2 + 1) ^ sw];
            ulonglong2 wA = __ldg((const ulonglong2*)(W + k * Hm + jb * 8));
            ulonglong2 wB = __ldg((const ulonglong2*)(W + k * Hm + jb * 8 + 4));
            float ev[8] = {ea.x, ea.y, ea.z, ea.w, eb.x, eb.y, eb.z, eb.w};
#pragma unroll
            for (int i = 0; i < 8; i++) {
                uint64_t ed = pack2(ev[i], ev[i]);
                acc[i][0] = ffma2(ed, wA.x, acc[i][0]);
                acc[i][1] = ffma2(ed, wA.y, acc[i][1]);
                acc[i][2] = ffma2(ed, wB.x, acc[i][2]);
                acc[i][3] = ffma2(ed, wB.y, acc[i][3]);
            }
        }
#pragma unroll
        for (int i = 0; i < 8; i++) {
            int n = n0 + nbk * 8 + i;
            if (n < N) {
                float2 a0 = unpack2(acc[i][0]), a1 = unpack2(acc[i][1]);
                float2 a2 = unpack2(acc[i][2]), a3 = unpack2(acc[i][3]);
                *(float4*)(O + (size_t)n * Hm + jb * 8)     = make_float4(a0.x, a0.y, a1.x, a1.y);
                *(float4*)(O + (size_t)n * Hm + jb * 8 + 4) = make_float4(a2.x, a2.y, a3.x, a3.y);
            }
        }
    }
}

// ---------------- per-layer: edge MLP — persistent tiles, smem weights -------
__global__ void __launch_bounds__(128, 4) k_edge(
    const int* __restrict__ src, const int* __restrict__ dst,
    const float* __restrict__ ein, float* __restrict__ eout,
    const float* __restrict__ W1c, const float* __restrict__ W2,
    const float* __restrict__ b2, const float* __restrict__ escale,
    int E, int nTiles)
{
    extern __shared__ float smem[];
    float* sEinT = smem;                  // [32][132], alive through GEMM1
    float* sHT   = smem;                  // [64][128] overlay
    __shared__ __align__(16) float sW1[Dm * Hm];   // 8KB
    __shared__ __align__(16) float sW2[Hm * Dm];   // 8KB
    __shared__ __align__(16) float sB2[Dm];
    __shared__ int sS[TEB], sD[TEB];
    __shared__ float sSc[Dm];
    int t = threadIdx.x;
    if (t < Dm) {
        sSc[t] = escale ? escale[t] * rsqrtf(1.0f + 1e-5f) : 1.0f;
        sB2[t] = b2[t];
    }
    for (int i = t; i < Dm * Hm; i += TEB) { sW1[i] = W1c[i]; sW2[i] = W2[i]; }
    int jb = t & 7, ebk = t >> 3;         // ebk in [0,16)
    int l8 = t & 7, g8 = t >> 3;

    for (int tile = blockIdx.x; tile < nTiles; tile += gridDim.x) {
        int e0 = tile * TEB;
        __syncthreads();                  // prev tile's sHT/sD reads done; weights visible (1st iter)
        int ei = min(e0 + t, E - 1);
        sS[t] = src[ei]; sD[t] = dst[ei];

        // ---- stage Ein transposed, quad swizzle, BN scale fold ----
        {
            int k0 = l8 * 4;
            float s0 = sSc[k0], s1 = sSc[k0 + 1], s2 = sSc[k0 + 2], s3 = sSc[k0 + 3];
#pragma unroll 2
            for (int p = 0; p < 8; p++) {
                int eL = p * 16 + g8;
                int eg = min(e0 + eL, E - 1);
                float4 v = __ldg((const float4*)(ein + (size_t)eg * Dm) + l8);
                int col = (((eL >> 2) ^ l8) << 2) + (eL & 3);
                sEinT[(k0 + 0) * SEIN + col] = v.x * s0;
                sEinT[(k0 + 1) * SEIN + col] = v.y * s1;
                sEinT[(k0 + 2) * SEIN + col] = v.z * s2;
                sEinT[(k0 + 3) * SEIN + col] = v.w * s3;
            }
        }
        __syncthreads();                  // sS/sD + sEinT visible

        // ---- direct bias init: acc = A'[src] + B[dst] ----
        uint64_t acc[8][4];
#pragma unroll
        for (int i = 0; i < 8; i++) {
            int eL = ebk * 8 + i;
            const float4* pa = (const float4*)(g_A  + (size_t)sS[eL] * Hm + jb * 8);
            const float4* pb = (const float4*)(g_Bp + (size_t)sD[eL] * Hm + jb * 8);
            float4 a0 = __ldg(pa), a1 = __ldg(pa + 1);
            float4 b0 = __ldg(pb), b1 = __ldg(pb + 1);
            acc[i][0] = pack2(a0.x + b0.x, a0.y + b0.y);
            acc[i][1] = pack2(a0.z + b0.z, a0.w + b0.w);
            acc[i][2] = pack2(a1.x + b1.x, a1.y + b1.y);
            acc[i][3] = pack2(a1.z + b1.z, a1.w + b1.w);
        }

        // ---- GEMM1: H[128x64] = EinT^T @ W1c + bias (weights from smem) ----
#pragma unroll 4
        for (int k = 0; k < Dm; k++) {
            int sw = k >> 2;
            const float4* pe = (const float4*)(sEinT + k * SEIN);
            float4 ea = pe[(ebk * 2) ^ sw];
            float4 eb = pe[(ebk * 2 + 1) ^ sw];
            const ulonglong2* pw = (const ulonglong2*)(sW1 + k * Hm + jb * 8);
            ulonglong2 wA = pw[0], wB = pw[1];
            float ev[8] = {ea.x, ea.y, ea.z, ea.w, eb.x, eb.y, eb.z, eb.w};
#pragma unroll
            for (int i = 0; i < 8; i++) {
                uint64_t ed = pack2(ev[i], ev[i]);
                acc[i][0] = ffma2(ed, wA.x, acc[i][0]);
                acc[i][1] = ffma2(ed, wA.y, acc[i][1]);
                acc[i][2] = ffma2(ed, wB.x, acc[i][2]);
                acc[i][3] = ffma2(ed, wB.y, acc[i][3]);
            }
        }
        __syncthreads();                  // sEinT dead; overlay sHT

        // ---- relu + store H^T [64][128], quad swizzle q ^ jb ----
#pragma unroll
        for (int jj = 0; jj < 8; jj++) {
            int j = jb * 8 + jj;
            float f[8];
#pragma unroll
            for (int i = 0; i < 8; i++) {
                float2 v = unpack2(acc[i][jj >> 1]);
                f[i] = fmaxf((jj & 1) ? v.y : v.x, 0.f);
            }
            *(float4*)(sHT + j * 128 + (((ebk * 2)     ^ jb) << 2)) = make_float4(f[0], f[1], f[2], f[3]);
            *(float4*)(sHT + j * 128 + (((ebk * 2 + 1) ^ jb) << 2)) = make_float4(f[4], f[5], f[6], f[7]);
        }
        __syncthreads();

        // ---- GEMM2: OUT[128x32] = relu(H) @ W2 + b2 (weights from smem) ----
        uint64_t out[8][2];
        {
            ulonglong2 bb = *(const ulonglong2*)(sB2 + jb * 4);
#pragma unroll
            for (int i = 0; i < 8; i++) { out[i][0] = bb.x; out[i][1] = bb.y; }
        }
#pragma unroll 4
        for (int k = 0; k < Hm; k++) {
            int sw = (k >> 3) & 7;
            const float4* ph = (const float4*)(sHT + k * 128);
            float4 h0 = ph[(ebk * 2) ^ sw];
            float4 h1 = ph[(ebk * 2 + 1) ^ sw];
            ulonglong2 w = *(const ulonglong2*)(sW2 + k * Dm + jb * 4);
            float hv[8] = {h0.x, h0.y, h0.z, h0.w, h1.x, h1.y, h1.z, h1.w};
#pragma unroll
            for (int i = 0; i < 8; i++) {
                uint64_t hd = pack2(hv[i], hv[i]);
                out[i][0] = ffma2(hd, w.x, out[i][0]);
                out[i][1] = ffma2(hd, w.y, out[i][1]);
            }
        }
        // ---- epilogue: write e + fused RED into agg ----
#pragma unroll
        for (int i = 0; i < 8; i++) {
            int eL = ebk * 8 + i, eg = e0 + eL;
            if (eg < E) {
                float2 a = unpack2(out[i][0]); float2 b = unpack2(out[i][1]);
                *(float4*)(eout + (size_t)eg * Dm + jb * 4) = make_float4(a.x, a.y, b.x, b.y);
                red_add_v4(g_agg + (size_t)sD[eL] * Dm + jb * 4, a.x, a.y, b.x, b.y);
            }
        }
    }
}

// ---------------- per-layer: node MLP — 128-thread tiles ---------------------
__global__ void __launch_bounds__(128, 4) k_node(
    float* __restrict__ x, const int* __restrict__ batch,
    const float* __restrict__ W1, const float* __restrict__ W2, const float* __restrict__ b2,
    int N)
{
    extern __shared__ float smem[];
    float* sIn = smem;     // [64][132]: rows 0..31 = x^T, rows 32..63 = (agg*rd)^T
    float* sHT = smem;     // overlay after GEMM1: [64][128]
    __shared__ int sBt[TEB];
    int t = threadIdx.x;
    int n0 = blockIdx.x * TEB;
    sBt[t] = batch[min(n0 + t, N - 1)];
    {
        int l8 = t & 7, g8 = t >> 3, k0 = l8 * 4;
#pragma unroll 2
        for (int p = 0; p < 8; p++) {
            int nL = p * 16 + g8;
            int ngl = min(n0 + nL, N - 1);
            float4 vx = __ldg((const float4*)(x + (size_t)ngl * Dm) + l8);
            float rd = g_rdeg[ngl];
            float4 va = __ldg((const float4*)(g_agg + (size_t)ngl * Dm) + l8);
            int col = (((nL >> 2) ^ l8) << 2) + (nL & 3);
            sIn[(k0 + 0) * SXT + col] = vx.x;
            sIn[(k0 + 1) * SXT + col] = vx.y;
            sIn[(k0 + 2) * SXT + col] = vx.z;
            sIn[(k0 + 3) * SXT + col] = vx.w;
            sIn[(Dm + k0 + 0) * SXT + col] = va.x * rd;
            sIn[(Dm + k0 + 1) * SXT + col] = va.y * rd;
            sIn[(Dm + k0 + 2) * SXT + col] = va.z * rd;
            sIn[(Dm + k0 + 3) * SXT + col] = va.w * rd;
        }
    }
    __syncthreads();

    // ---- GEMM1: H[128x64] = In^T @ W1(rows 0..63) + hUn[batch] ----
    int jb = t & 7, nbk = t >> 3;
    uint64_t acc[8][4];
#pragma unroll
    for (int i = 0; i < 8; i++) {
        int bb = sBt[nbk * 8 + i];
        const ulonglong2* pb = (const ulonglong2*)(g_hUn + bb * Hm + jb * 8);
        ulonglong2 b0 = __ldg(pb), b1 = __ldg(pb + 1);
        acc[i][0] = b0.x; acc[i][1] = b0.y; acc[i][2] = b1.x; acc[i][3] = b1.y;
    }
#pragma unroll 4
    for (int k = 0; k < 2 * Dm; k++) {
        int sw = (k >> 2) & 7;
        const float4* pe = (const float4*)(sIn + k * SXT);
        float4 ea = pe[(nbk * 2) ^ sw];
        float4 eb = pe[(nbk * 2 + 1) ^ sw];
        ulonglong2 wA = __ldg((const ulonglong2*)(W1 + k * Hm + jb * 8));
        ulonglong2 wB = __ldg((const ulonglong2*)(W1 + k * Hm + jb * 8 + 4));
        float ev[8] = {ea.x, ea.y, ea.z, ea.w, eb.x, eb.y, eb.z, eb.w};
#pragma unroll
        for (int i = 0; i < 8; i++) {
            uint64_t ed = pack2(ev[i], ev[i]);
            acc[i][0] = ffma2(ed, wA.x, acc[i][0]);
            acc[i][1] = ffma2(ed, wA.y, acc[i][1]);
            acc[i][2] = ffma2(ed, wB.x, acc[i][2]);
            acc[i][3] = ffma2(ed, wB.y, acc[i][3]);
        }
    }
    __syncthreads();   // all reads of sIn complete before HT overlay

#pragma unroll
    for (int jj = 0; jj < 8; jj++) {
        int j = jb * 8 + jj;
        float f[8];
#pragma unroll
        for (int i = 0; i < 8; i++) {
            float2 v = unpack2(acc[i][jj >> 1]);
            f[i] = fmaxf((jj & 1) ? v.y : v.x, 0.f);
        }
        *(float4*)(sHT + j * 128 + (((nbk * 2)     ^ jb) << 2)) = make_float4(f[0], f[1], f[2], f[3]);
        *(float4*)(sHT + j * 128 + (((nbk * 2 + 1) ^ jb) << 2)) = make_float4(f[4], f[5], f[6], f[7]);
    }
    __syncthreads();

    // ---- GEMM2: OUT[128x32] = relu(H) @ W2 + b2 ----
    uint64_t out[8][2];
    {
        ulonglong2 bb = __ldg((const ulonglong2*)(b2 + jb * 4));
#pragma unroll
        for (int i = 0; i < 8; i++) { out[i][0] = bb.x; out[i][1] = bb.y; }
    }
#pragma unroll 4
    for (int k = 0; k < Hm; k++) {
        int sw = (k >> 3) & 7;
        const float4* ph = (const float4*)(sHT + k * 128);
        float4 h0 = ph[(nbk * 2) ^ sw];
        float4 h1 = ph[(nbk * 2 + 1) ^ sw];
        ulonglong2 w = __ldg((const ulonglong2*)(W2 + k * Dm + jb * 4));
        float hv[8] = {h0.x, h0.y, h0.z, h0.w, h1.x, h1.y, h1.z, h1.w};
#pragma unroll
        for (int i = 0; i < 8; i++) {
            uint64_t hd = pack2(hv[i], hv[i]);
            out[i][0] = ffma2(hd, w.x, out[i][0]);
            out[i][1] = ffma2(hd, w.y, out[i][1]);
        }
    }
#pragma unroll
    for (int i = 0; i < 8; i++) {
        int n = n0 + nbk * 8 + i;
        if (n < N) {
            float2 a = unpack2(out[i][0]); float2 b = unpack2(out[i][1]);
            *(float4*)(x + (size_t)n * Dm + jb * 4) = make_float4(a.x, a.y, b.x, b.y);
        }
    }
}

// ---------------- per-layer: global MLP (sorted-batch segment reduce) --------
static __device__ __forceinline__ int lowerb(const int* __restrict__ a, int n, int v) {
    int lo = 0, hi = n;
    while (lo < hi) { int m = (lo + hi) >> 1; if (a[m] < v) lo = m + 1; else hi = m; }
    return lo;
}
__global__ void k_glob(float* __restrict__ u, const float* __restrict__ x,
                       const int* __restrict__ batch,
                       const float* __restrict__ W1, const float* __restrict__ b1,
                       const float* __restrict__ W2, const float* __restrict__ b2, int N) {
    int b = blockIdx.x, t = threadIdx.x;       // 128 threads
    __shared__ int sLo, sHi;
    if (t == 0) { sLo = lowerb(batch, N, b); sHi = lowerb(batch, N, b + 1); }
    __syncthreads();
    int lo = sLo, hi = sHi;
    float cnt = fmaxf((float)(hi - lo), 1.0f);
    int c = t & 31, g = t >> 5;
    float acc = 0.f;
    for (int r = lo + g; r < hi; r += 4) acc += x[(size_t)r * Dm + c];
    __shared__ float sred[4][Dm];
    sred[g][c] = acc;
    __syncthreads();
    __shared__ float su[2 * Dm];
    __shared__ float sh[Hm];
    if (t < Dm) su[t] = u[b * Dm + t];
    else if (t < 2 * Dm) {
        int cc = t - Dm;
        su[t] = (sred[0][cc] + sred[1][cc] + sred[2][cc] + sred[3][cc]) / cnt;
    }
    __syncthreads();
    if (t < Hm) {
        float h = b1[t];
#pragma unroll 4
        for (int k = 0; k < 2 * Dm; k++) h += su[k] * W1[k * Hm + t];
        sh[t] = fmaxf(h, 0.f);
    }
    __syncthreads();
    if (t < Dm) {
        float o = b2[t];
#pragma unroll 4
        for (int k = 0; k < Hm; k++) o += sh[k] * W2[k * Dm + t];
        u[b * Dm + t] = o;
    }
}

// ---------------- launch -----------------------------------------------------
extern "C" void kernel_launch(void* const* d_in, const int* in_sizes, int n_in,
                              void* d_out, int out_size) {
    const float* node_feats = (const float*)d_in[0];
    const int*   edge_index = (const int*)  d_in[1];
    const float* edge_feats = (const float*)d_in[2];
    const float* glob_feats = (const float*)d_in[3];
    const int*   batch      = (const int*)  d_in[4];
    const float* ngam = (const float*)d_in[5];
    const float* nbet = (const float*)d_in[6];
    const float* egam = (const float*)d_in[7];
    const float* ebet = (const float*)d_in[8];
    const float* ggam = (const float*)d_in[9];
    const float* gbet = (const float*)d_in[10];
    const float* eW1 = (const float*)d_in[11];
    const float* eb1 = (const float*)d_in[12];
    const float* eW2 = (const float*)d_in[13];
    const float* eb2 = (const float*)d_in[14];
    const float* nW1 = (const float*)d_in[15];
    const float* nb1 = (const float*)d_in[16];
    const float* nW2 = (const float*)d_in[17];
    const float* nb2 = (const float*)d_in[18];
    const float* gW1 = (const float*)d_in[19];
    const float* gb1 = (const float*)d_in[20];
    const float* gW2 = (const float*)d_in[21];
    const float* gb2 = (const float*)d_in[22];

    const int N = in_sizes[0] / Dm;
    const int E = in_sizes[2] / Dm;
    const int B = in_sizes[3] / Dm;

    float* x = (float*)d_out;
    float* e = x + (size_t)N * Dm;
    float* u = e + (size_t)E * Dm;
    const int* src = edge_index;
    const int* dst = edge_index + E;

    const int TB = 256;
    int XB = (N * 8 + TB - 1) / TB;
    int gE = (E + TB - 1) / TB;
    int gN128 = (N + TEB - 1) / TEB;
    int nTiles = (E + TEB - 1) / TEB;
    int gEdge = nTiles < 592 ? nTiles : 592;   // 4 blocks/SM x 148 SMs

    // Opt-in: k_edge static (~17.7KB) + dynamic (32KB) exceeds the 48KB
    // default combined limit — the attribute moves it to the large carveout.
    cudaFuncSetAttribute(k_edge, cudaFuncAttributeMaxDynamicSharedMemorySize, SMEM_EDGE_BYTES);
    cudaFuncSetAttribute(k_node, cudaFuncAttributeMaxDynamicSharedMemorySize, SMEM_NODE_BYTES);

    // launch 0: BN(x,u) + zero deg
    k_bn_xu<<<XB + 1, TB>>>((const float4*)node_feats, (const float4*)glob_feats,
                            (float4*)x, (float4*)u, ngam, nbet, ggam, gbet, N, B, XB);
    // launch 1: deg count + layer-0 hU
    k_deg_hu<<<gE + 1, TB>>>(dst, u, eW1, eb1, nW1, nb1, ebet, E, B);

    for (int l = 0; l < 3; l++) {
        const float* eW1l = eW1 + (size_t)l * 4 * Dm * Hm;   // (128,64)
        const float* nW1l = nW1 + (size_t)l * 3 * Dm * Hm;   // (96,64)
        const float* gW1l = gW1 + (size_t)l * 2 * Dm * Hm;   // (64,64)
        if (l > 0)
            k_hu<<<1, Hm>>>(u, eW1l, eb1 + l * Hm, nW1l, nb1 + l * Hm, B);
        k_pre<<<gN128, TEB>>>(x, batch, eW1l, N);            // launch 2 (l=0)
        k_edge<<<gEdge, TEB, SMEM_EDGE_BYTES>>>(src, dst,    // launch 3 (l=0) — profiled
                           (l == 0) ? edge_feats : e, e,
                           eW1l + 2 * Dm * Hm,               // rows 64..95 (e part)
                           eW2 + (size_t)l * Hm * Dm, eb2 + l * Dm,
                           (l == 0) ? egam : (const float*)nullptr, E, nTiles);
        k_node<<<gN128, TEB, SMEM_NODE_BYTES>>>(x, batch, nW1l,
                           nW2 + (size_t)l * Hm * Dm, nb2 + l * Dm, N);
        k_glob<<<B, 128>>>(u, x, batch, gW1l, gb1 + l * Hm,
                           gW2 + (size_t)l * Hm * Dm, gb2 + l * Dm, N);
    }
}

// round 13
// speedup vs baseline: 1.1065x; 1.0753x over previous
#include <cuda_runtime.h>
#include <cuda_fp16.h>
#include <cstdint>

#define Dm 32
#define Hm 64
#define NMAX 50000
#define BMAX 16
#define TEB 128
#define SEIN 132
#define SXT 132
#define SMEM_EDGE_BYTES (64 * 128 * 4)      // sHT [64][128] dominates; sEinT [32][132] aliases
#define SMEM_NODE_BYTES (64 * SXT * 4)      // sIn [64][132]; sHT [64][128] aliases

// ---------------- scratch ----------------------------------------------------
__device__ __align__(16) __half g_A [NMAX * Hm];   // fp16: A' = x@W1a + hU[batch]
__device__ __align__(16) __half g_Bp[NMAX * Hm];   // fp16: B  = x@W1b
__device__ __align__(16) float g_agg[NMAX * Dm];
__device__ __align__(16) float g_hU [BMAX * Hm];
__device__ __align__(16) float g_hUn[BMAX * Hm];
__device__ float g_deg [NMAX];
__device__ float g_rdeg[NMAX];

// ---------------- packed f32x2 helpers ---------------------------------------
static __device__ __forceinline__ uint64_t ffma2(uint64_t a, uint64_t b, uint64_t c) {
    uint64_t d; asm("fma.rn.f32x2 %0, %1, %2, %3;" : "=l"(d) : "l"(a), "l"(b), "l"(c));
    return d;
}
static __device__ __forceinline__ uint64_t pack2(float lo, float hi) {
    uint64_t r; asm("mov.b64 %0, {%1, %2};" : "=l"(r) : "f"(lo), "f"(hi));
    return r;
}
static __device__ __forceinline__ float2 unpack2(uint64_t v) {
    float lo, hi; asm("mov.b64 {%0, %1}, %2;" : "=f"(lo), "=f"(hi) : "l"(v));
    float2 f; f.x = lo; f.y = hi; return f;
}
static __device__ __forceinline__ void red_add_v4(float* p, float a, float b, float c, float d) {
    asm volatile("red.global.add.v4.f32 [%0], {%1, %2, %3, %4};"
                 :: "l"(p), "f"(a), "f"(b), "f"(c), "f"(d) : "memory");
}

// ---------------- launch 0: BN for x and u (+ zero deg) ----------------------
__global__ void k_bn_xu(const float4* __restrict__ nf, const float4* __restrict__ gf,
                        float4* __restrict__ x, float4* __restrict__ u,
                        const float* __restrict__ ngam, const float* __restrict__ nbet,
                        const float* __restrict__ ggam, const float* __restrict__ gbet,
                        int N, int B, int XB) {
    const float r = rsqrtf(1.0f + 1e-5f);
    int bid = blockIdx.x, t = threadIdx.x;
    const float4* in; float4* out; const float* gm; const float* bt; int i4, lim;
    if (bid < XB) { i4 = bid * 256 + t; lim = N * 8; in = nf; out = x; gm = ngam; bt = nbet;
                    if (i4 < N) g_deg[i4] = 0.0f; }
    else          { i4 = t;             lim = B * 8; in = gf; out = u; gm = ggam; bt = gbet; }
    if (i4 >= lim) return;
    float4 v = in[i4];
    int c = (i4 * 4) & (Dm - 1);
    v.x = v.x * (gm[c + 0] * r) + bt[c + 0];
    v.y = v.y * (gm[c + 1] * r) + bt[c + 1];
    v.z = v.z * (gm[c + 2] * r) + bt[c + 2];
    v.w = v.w * (gm[c + 3] * r) + bt[c + 3];
    out[i4] = v;
}

// ---------------- hU/hUn body -------------------------------------------------
static __device__ __forceinline__ void hu_body(
    const float* __restrict__ u,
    const float* __restrict__ eW1, const float* __restrict__ eb1,
    const float* __restrict__ nW1, const float* __restrict__ nb1,
    const float* __restrict__ ebet, int B, int j)
{
    float c = 0.f;
    if (ebet) {            // layer 0: BN shift of e folded through W1c
#pragma unroll 4
        for (int k = 0; k < Dm; k++) c += ebet[k] * eW1[(2 * Dm + k) * Hm + j];
    }
    for (int b = 0; b < B; b++) {
        float hu = eb1[j] + c, hun = nb1[j];
#pragma unroll 4
        for (int k = 0; k < Dm; k++) {
            float uv = u[b * Dm + k];
            hu  += uv * eW1[(3 * Dm + k) * Hm + j];
            hun += uv * nW1[(2 * Dm + k) * Hm + j];
        }
        g_hU [b * Hm + j] = hu;
        g_hUn[b * Hm + j] = hun;
    }
}

// ---------------- launch 1: deg count + layer-0 hU ----------------------------
__global__ void k_deg_hu(const int* __restrict__ dst, const float* __restrict__ u,
                         const float* __restrict__ eW1, const float* __restrict__ eb1,
                         const float* __restrict__ nW1, const float* __restrict__ nb1,
                         const float* __restrict__ ebet, int E, int B) {
    if (blockIdx.x == gridDim.x - 1) {
        if (threadIdx.x < Hm) hu_body(u, eW1, eb1, nW1, nb1, ebet, B, threadIdx.x);
        return;
    }
    int i = blockIdx.x * blockDim.x + threadIdx.x;
    if (i < E) atomicAdd(&g_deg[dst[i]], 1.0f);
}

// layers 1,2: standalone hU
__global__ void k_hu(const float* __restrict__ u,
                     const float* __restrict__ eW1, const float* __restrict__ eb1,
                     const float* __restrict__ nW1, const float* __restrict__ nb1, int B) {
    if (threadIdx.x < Hm) hu_body(u, eW1, eb1, nW1, nb1, nullptr, B, threadIdx.x);
}

// ---------------- per-layer: A'/B precompute (tiled GEMM, fp16 out) ----------
__global__ void __launch_bounds__(128, 4) k_pre(const float* __restrict__ x,
                                                const int* __restrict__ batch,
                                                const float* __restrict__ eW1, int N) {
    __shared__ __align__(16) float sX[32 * SXT];
    __shared__ int sBt[TEB];
    int t = threadIdx.x;
    int n0 = blockIdx.x * TEB;
    sBt[t] = batch[min(n0 + t, N - 1)];
    if (n0 + t < N) g_rdeg[n0 + t] = 1.0f / fmaxf(g_deg[n0 + t], 1.0f);
    {   // zero this block's agg region
        float4 z = make_float4(0.f, 0.f, 0.f, 0.f);
        float4* pz = (float4*)(g_agg + (size_t)n0 * Dm);
        int lim4 = min(TEB, N - n0) * 8;
        for (int i = t; i < lim4; i += TEB) pz[i] = z;
    }
    {   // stage x^T, quad swizzle
        int l8 = t & 7, g8 = t >> 3, k0 = l8 * 4;   // g8 in [0,16)
#pragma unroll 2
        for (int p = 0; p < 8; p++) {
            int nL = p * 16 + g8;
            int ngl = min(n0 + nL, N - 1);
            float4 v = __ldg((const float4*)(x + (size_t)ngl * Dm) + l8);
            int col = (((nL >> 2) ^ l8) << 2) + (nL & 3);
            sX[(k0 + 0) * SXT + col] = v.x;
            sX[(k0 + 1) * SXT + col] = v.y;
            sX[(k0 + 2) * SXT + col] = v.z;
            sX[(k0 + 3) * SXT + col] = v.w;
        }
    }
    __syncthreads();

    int jb = t & 7, nbk = t >> 3;       // nbk in [0,16)
    uint64_t acc[8][4];
#pragma unroll
    for (int g = 0; g < 2; g++) {       // g=0: A' (rows 0..31, hU bias); g=1: B (rows 32..63)
        const float* W = eW1 + g * Dm * Hm;
        __half* O = g ? g_Bp : g_A;
#pragma unroll
        for (int i = 0; i < 8; i++) {
            if (g == 0) {
                int bb = sBt[nbk * 8 + i];
                const ulonglong2* pb = (const ulonglong2*)(g_hU + bb * Hm + jb * 8);
                ulonglong2 b0 = __ldg(pb), b1 = __ldg(pb + 1);
                acc[i][0] = b0.x; acc[i][1] = b0.y; acc[i][2] = b1.x; acc[i][3] = b1.y;
            } else {
                acc[i][0] = acc[i][1] = acc[i][2] = acc[i][3] = 0ull;
            }
        }
#pragma unroll 4
        for (int k = 0; k < Dm; k++) {
            int sw = k >> 2;
            const float4* pe = (const float4*)(sX + k * SXT);
            float4 ea = pe[(nbk * 2) ^ sw];
            float4 eb = pe[(nbk * 2 + 1) ^ sw];
            ulonglong2 wA = __ldg((const ulonglong2*)(W + k * Hm + jb * 8));
            ulonglong2 wB = __ldg((const ulonglong2*)(W + k * Hm + jb * 8 + 4));
            float ev[8] = {ea.x, ea.y, ea.z, ea.w, eb.x, eb.y, eb.z, eb.w};
#pragma unroll
            for (int i = 0; i < 8; i++) {
                uint64_t ed = pack2(ev[i], ev[i]);
                acc[i][0] = ffma2(ed, wA.x, acc[i][0]);
                acc[i][1] = ffma2(ed, wA.y, acc[i][1]);
                acc[i][2] = ffma2(ed, wB.x, acc[i][2]);
                acc[i][3] = ffma2(ed, wB.y, acc[i][3]);
            }
        }
#pragma unroll
        for (int i = 0; i < 8; i++) {
            int n = n0 + nbk * 8 + i;
            if (n < N) {
                float2 f0 = unpack2(acc[i][0]), f1 = unpack2(acc[i][1]);
                float2 f2 = unpack2(acc[i][2]), f3 = unpack2(acc[i][3]);
                __half2 hs[4];
                hs[0] = __floats2half2_rn(f0.x, f0.y);
                hs[1] = __floats2half2_rn(f1.x, f1.y);
                hs[2] = __floats2half2_rn(f2.x, f2.y);
                hs[3] = __floats2half2_rn(f3.x, f3.y);
                *(uint4*)(O + (size_t)n * Hm + jb * 8) = *(uint4*)hs;
            }
        }
    }
}

// ---------------- per-layer: edge MLP — persistent tiles, fp16 bias gather ---
__global__ void __launch_bounds__(128, 4) k_edge(
    const int* __restrict__ src, const int* __restrict__ dst,
    const float* __restrict__ ein, float* __restrict__ eout,
    const float* __restrict__ W1c, const float* __restrict__ W2,
    const float* __restrict__ b2, const float* __restrict__ escale,
    int E, int nTiles)
{
    extern __shared__ float smem[];
    float* sEinT = smem;                  // [32][132], alive through GEMM1
    float* sHT   = smem;                  // [64][128] overlay
    __shared__ __align__(16) float sW1[Dm * Hm];   // 8KB
    __shared__ __align__(16) float sW2[Hm * Dm];   // 8KB
    __shared__ __align__(16) float sB2[Dm];
    __shared__ int sS[TEB], sD[TEB];
    __shared__ float sSc[Dm];
    int t = threadIdx.x;
    if (t < Dm) {
        sSc[t] = escale ? escale[t] * rsqrtf(1.0f + 1e-5f) : 1.0f;
        sB2[t] = b2[t];
    }
    for (int i = t; i < Dm * Hm; i += TEB) { sW1[i] = W1c[i]; sW2[i] = W2[i]; }
    int jb = t & 7, ebk = t >> 3;         // ebk in [0,16)
    int l8 = t & 7, g8 = t >> 3;

    for (int tile = blockIdx.x; tile < nTiles; tile += gridDim.x) {
        int e0 = tile * TEB;
        __syncthreads();                  // prev tile's sHT/sD reads done; weights visible (1st iter)
        int ei = min(e0 + t, E - 1);
        sS[t] = src[ei]; sD[t] = dst[ei];

        // ---- stage Ein transposed, quad swizzle, BN scale fold ----
        {
            int k0 = l8 * 4;
            float s0 = sSc[k0], s1 = sSc[k0 + 1], s2 = sSc[k0 + 2], s3 = sSc[k0 + 3];
#pragma unroll 2
            for (int p = 0; p < 8; p++) {
                int eL = p * 16 + g8;
                int eg = min(e0 + eL, E - 1);
                float4 v = __ldg((const float4*)(ein + (size_t)eg * Dm) + l8);
                int col = (((eL >> 2) ^ l8) << 2) + (eL & 3);
                sEinT[(k0 + 0) * SEIN + col] = v.x * s0;
                sEinT[(k0 + 1) * SEIN + col] = v.y * s1;
                sEinT[(k0 + 2) * SEIN + col] = v.z * s2;
                sEinT[(k0 + 3) * SEIN + col] = v.w * s3;
            }
        }
        __syncthreads();                  // sS/sD + sEinT visible

        // ---- direct bias init: acc = A'[src] + B[dst]  (fp16 gathers) ----
        uint64_t acc[8][4];
#pragma unroll
        for (int i = 0; i < 8; i++) {
            int eL = ebk * 8 + i;
            uint4 ua = __ldg((const uint4*)(g_A  + (size_t)sS[eL] * Hm + jb * 8));
            uint4 ub = __ldg((const uint4*)(g_Bp + (size_t)sD[eL] * Hm + jb * 8));
            const __half2* ha = (const __half2*)&ua;
            const __half2* hb = (const __half2*)&ub;
#pragma unroll
            for (int q = 0; q < 4; q++) {
                float2 fa = __half22float2(ha[q]);
                float2 fb = __half22float2(hb[q]);
                acc[i][q] = pack2(fa.x + fb.x, fa.y + fb.y);
            }
        }

        // ---- GEMM1: H[128x64] = EinT^T @ W1c + bias (weights from smem) ----
#pragma unroll 4
        for (int k = 0; k < Dm; k++) {
            int sw = k >> 2;
            const float4* pe = (const float4*)(sEinT + k * SEIN);
            float4 ea = pe[(ebk * 2) ^ sw];
            float4 eb = pe[(ebk * 2 + 1) ^ sw];
            const ulonglong2* pw = (const ulonglong2*)(sW1 + k * Hm + jb * 8);
            ulonglong2 wA = pw[0], wB = pw[1];
            float ev[8] = {ea.x, ea.y, ea.z, ea.w, eb.x, eb.y, eb.z, eb.w};
#pragma unroll
            for (int i = 0; i < 8; i++) {
                uint64_t ed = pack2(ev[i], ev[i]);
                acc[i][0] = ffma2(ed, wA.x, acc[i][0]);
                acc[i][1] = ffma2(ed, wA.y, acc[i][1]);
                acc[i][2] = ffma2(ed, wB.x, acc[i][2]);
                acc[i][3] = ffma2(ed, wB.y, acc[i][3]);
            }
        }
        __syncthreads();                  // sEinT dead; overlay sHT

        // ---- relu + store H^T [64][128], quad swizzle q ^ jb ----
#pragma unroll
        for (int jj = 0; jj < 8; jj++) {
            int j = jb * 8 + jj;
            float f[8];
#pragma unroll
            for (int i = 0; i < 8; i++) {
                float2 v = unpack2(acc[i][jj >> 1]);
                f[i] = fmaxf((jj & 1) ? v.y : v.x, 0.f);
            }
            *(float4*)(sHT + j * 128 + (((ebk * 2)     ^ jb) << 2)) = make_float4(f[0], f[1], f[2], f[3]);
            *(float4*)(sHT + j * 128 + (((ebk * 2 + 1) ^ jb) << 2)) = make_float4(f[4], f[5], f[6], f[7]);
        }
        __syncthreads();

        // ---- GEMM2: OUT[128x32] = relu(H) @ W2 + b2 (weights from smem) ----
        uint64_t out[8][2];
        {
            ulonglong2 bb = *(const ulonglong2*)(sB2 + jb * 4);
#pragma unroll
            for (int i = 0; i < 8; i++) { out[i][0] = bb.x; out[i][1] = bb.y; }
        }
#pragma unroll 4
        for (int k = 0; k < Hm; k++) {
            int sw = (k >> 3) & 7;
            const float4* ph = (const float4*)(sHT + k * 128);
            float4 h0 = ph[(ebk * 2) ^ sw];
            float4 h1 = ph[(ebk * 2 + 1) ^ sw];
            ulonglong2 w = *(const ulonglong2*)(sW2 + k * Dm + jb * 4);
            float hv[8] = {h0.x, h0.y, h0.z, h0.w, h1.x, h1.y, h1.z, h1.w};
#pragma unroll
            for (int i = 0; i < 8; i++) {
                uint64_t hd = pack2(hv[i], hv[i]);
                out[i][0] = ffma2(hd, w.x, out[i][0]);
                out[i][1] = ffma2(hd, w.y, out[i][1]);
            }
        }
        // ---- epilogue: write e + fused RED into agg ----
#pragma unroll
        for (int i = 0; i < 8; i++) {
            int eL = ebk * 8 + i, eg = e0 + eL;
            if (eg < E) {
                float2 a = unpack2(out[i][0]); float2 b = unpack2(out[i][1]);
                *(float4*)(eout + (size_t)eg * Dm + jb * 4) = make_float4(a.x, a.y, b.x, b.y);
                red_add_v4(g_agg + (size_t)sD[eL] * Dm + jb * 4, a.x, a.y, b.x, b.y);
            }
        }
    }
}

// ---------------- per-layer: node MLP — 128-thread tiles ---------------------
__global__ void __launch_bounds__(128, 4) k_node(
    float* __restrict__ x, const int* __restrict__ batch,
    const float* __restrict__ W1, const float* __restrict__ W2, const float* __restrict__ b2,
    int N)
{
    extern __shared__ float smem[];
    float* sIn = smem;     // [64][132]: rows 0..31 = x^T, rows 32..63 = (agg*rd)^T
    float* sHT = smem;     // overlay after GEMM1: [64][128]
    __shared__ int sBt[TEB];
    int t = threadIdx.x;
    int n0 = blockIdx.x * TEB;
    sBt[t] = batch[min(n0 + t, N - 1)];
    {
        int l8 = t & 7, g8 = t >> 3, k0 = l8 * 4;
#pragma unroll 2
        for (int p = 0; p < 8; p++) {
            int nL = p * 16 + g8;
            int ngl = min(n0 + nL, N - 1);
            float4 vx = __ldg((const float4*)(x + (size_t)ngl * Dm) + l8);
            float rd = g_rdeg[ngl];
            float4 va = __ldg((const float4*)(g_agg + (size_t)ngl * Dm) + l8);
            int col = (((nL >> 2) ^ l8) << 2) + (nL & 3);
            sIn[(k0 + 0) * SXT + col] = vx.x;
            sIn[(k0 + 1) * SXT + col] = vx.y;
            sIn[(k0 + 2) * SXT + col] = vx.z;
            sIn[(k0 + 3) * SXT + col] = vx.w;
            sIn[(Dm + k0 + 0) * SXT + col] = va.x * rd;
            sIn[(Dm + k0 + 1) * SXT + col] = va.y * rd;
            sIn[(Dm + k0 + 2) * SXT + col] = va.z * rd;
            sIn[(Dm + k0 + 3) * SXT + col] = va.w * rd;
        }
    }
    __syncthreads();

    // ---- GEMM1: H[128x64] = In^T @ W1(rows 0..63) + hUn[batch] ----
    int jb = t & 7, nbk = t >> 3;
    uint64_t acc[8][4];
#pragma unroll
    for (int i = 0; i < 8; i++) {
        int bb = sBt[nbk * 8 + i];
        const ulonglong2* pb = (const ulonglong2*)(g_hUn + bb * Hm + jb * 8);
        ulonglong2 b0 = __ldg(pb), b1 = __ldg(pb + 1);
        acc[i][0] = b0.x; acc[i][1] = b0.y; acc[i][2] = b1.x; acc[i][3] = b1.y;
    }
#pragma unroll 4
    for (int k = 0; k < 2 * Dm; k++) {
        int sw = (k >> 2) & 7;
        const float4* pe = (const float4*)(sIn + k * SXT);
        float4 ea = pe[(nbk * 2) ^ sw];
        float4 eb = pe[(nbk * 2 + 1) ^ sw];
        ulonglong2 wA = __ldg((const ulonglong2*)(W1 + k * Hm + jb * 8));
        ulonglong2 wB = __ldg((const ulonglong2*)(W1 + k * Hm + jb * 8 + 4));
        float ev[8] = {ea.x, ea.y, ea.z, ea.w, eb.x, eb.y, eb.z, eb.w};
#pragma unroll
        for (int i = 0; i < 8; i++) {
            uint64_t ed = pack2(ev[i], ev[i]);
            acc[i][0] = ffma2(ed, wA.x, acc[i][0]);
            acc[i][1] = ffma2(ed, wA.y, acc[i][1]);
            acc[i][2] = ffma2(ed, wB.x, acc[i][2]);
            acc[i][3] = ffma2(ed, wB.y, acc[i][3]);
        }
    }
    __syncthreads();   // all reads of sIn complete before HT overlay

#pragma unroll
    for (int jj = 0; jj < 8; jj++) {
        int j = jb * 8 + jj;
        float f[8];
#pragma unroll
        for (int i = 0; i < 8; i++) {
            float2 v = unpack2(acc[i][jj >> 1]);
            f[i] = fmaxf((jj & 1) ? v.y : v.x, 0.f);
        }
        *(float4*)(sHT + j * 128 + (((nbk * 2)     ^ jb) << 2)) = make_float4(f[0], f[1], f[2], f[3]);
        *(float4*)(sHT + j * 128 + (((nbk * 2 + 1) ^ jb) << 2)) = make_float4(f[4], f[5], f[6], f[7]);
    }
    __syncthreads();

    // ---- GEMM2: OUT[128x32] = relu(H) @ W2 + b2 ----
    uint64_t out[8][2];
    {
        ulonglong2 bb = __ldg((const ulonglong2*)(b2 + jb * 4));
#pragma unroll
        for (int i = 0; i < 8; i++) { out[i][0] = bb.x; out[i][1] = bb.y; }
    }
#pragma unroll 4
    for (int k = 0; k < Hm; k++) {
        int sw = (k >> 3) & 7;
        const float4* ph = (const float4*)(sHT + k * 128);
        float4 h0 = ph[(nbk * 2) ^ sw];
        float4 h1 = ph[(nbk * 2 + 1) ^ sw];
        ulonglong2 w = __ldg((const ulonglong2*)(W2 + k * Dm + jb * 4));
        float hv[8] = {h0.x, h0.y, h0.z, h0.w, h1.x, h1.y, h1.z, h1.w};
#pragma unroll
        for (int i = 0; i < 8; i++) {
            uint64_t hd = pack2(hv[i], hv[i]);
            out[i][0] = ffma2(hd, w.x, out[i][0]);
            out[i][1] = ffma2(hd, w.y, out[i][1]);
        }
    }
#pragma unroll
    for (int i = 0; i < 8; i++) {
        int n = n0 + nbk * 8 + i;
        if (n < N) {
            float2 a = unpack2(out[i][0]); float2 b = unpack2(out[i][1]);
            *(float4*)(x + (size_t)n * Dm + jb * 4) = make_float4(a.x, a.y, b.x, b.y);
        }
    }
}

// ---------------- per-layer: global MLP (sorted-batch segment reduce) --------
static __device__ __forceinline__ int lowerb(const int* __restrict__ a, int n, int v) {
    int lo = 0, hi = n;
    while (lo < hi) { int m = (lo + hi) >> 1; if (a[m] < v) lo = m + 1; else hi = m; }
    return lo;
}
__global__ void k_glob(float* __restrict__ u, const float* __restrict__ x,
                       const int* __restrict__ batch,
                       const float* __restrict__ W1, const float* __restrict__ b1,
                       const float* __restrict__ W2, const float* __restrict__ b2, int N) {
    int b = blockIdx.x, t = threadIdx.x;       // 128 threads
    __shared__ int sLo, sHi;
    if (t == 0) { sLo = lowerb(batch, N, b); sHi = lowerb(batch, N, b + 1); }
    __syncthreads();
    int lo = sLo, hi = sHi;
    float cnt = fmaxf((float)(hi - lo), 1.0f);
    int c = t & 31, g = t >> 5;
    float acc = 0.f;
    for (int r = lo + g; r < hi; r += 4) acc += x[(size_t)r * Dm + c];
    __shared__ float sred[4][Dm];
    sred[g][c] = acc;
    __syncthreads();
    __shared__ float su[2 * Dm];
    __shared__ float sh[Hm];
    if (t < Dm) su[t] = u[b * Dm + t];
    else if (t < 2 * Dm) {
        int cc = t - Dm;
        su[t] = (sred[0][cc] + sred[1][cc] + sred[2][cc] + sred[3][cc]) / cnt;
    }
    __syncthreads();
    if (t < Hm) {
        float h = b1[t];
#pragma unroll 4
        for (int k = 0; k < 2 * Dm; k++) h += su[k] * W1[k * Hm + t];
        sh[t] = fmaxf(h, 0.f);
    }
    __syncthreads();
    if (t < Dm) {
        float o = b2[t];
#pragma unroll 4
        for (int k = 0; k < Hm; k++) o += sh[k] * W2[k * Dm + t];
        u[b * Dm + t] = o;
    }
}

// ---------------- launch -----------------------------------------------------
extern "C" void kernel_launch(void* const* d_in, const int* in_sizes, int n_in,
                              void* d_out, int out_size) {
    const float* node_feats = (const float*)d_in[0];
    const int*   edge_index = (const int*)  d_in[1];
    const float* edge_feats = (const float*)d_in[2];
    const float* glob_feats = (const float*)d_in[3];
    const int*   batch      = (const int*)  d_in[4];
    const float* ngam = (const float*)d_in[5];
    const float* nbet = (const float*)d_in[6];
    const float* egam = (const float*)d_in[7];
    const float* ebet = (const float*)d_in[8];
    const float* ggam = (const float*)d_in[9];
    const float* gbet = (const float*)d_in[10];
    const float* eW1 = (const float*)d_in[11];
    const float* eb1 = (const float*)d_in[12];
    const float* eW2 = (const float*)d_in[13];
    const float* eb2 = (const float*)d_in[14];
    const float* nW1 = (const float*)d_in[15];
    const float* nb1 = (const float*)d_in[16];
    const float* nW2 = (const float*)d_in[17];
    const float* nb2 = (const float*)d_in[18];
    const float* gW1 = (const float*)d_in[19];
    const float* gb1 = (const float*)d_in[20];
    const float* gW2 = (const float*)d_in[21];
    const float* gb2 = (const float*)d_in[22];

    const int N = in_sizes[0] / Dm;
    const int E = in_sizes[2] / Dm;
    const int B = in_sizes[3] / Dm;

    float* x = (float*)d_out;
    float* e = x + (size_t)N * Dm;
    float* u = e + (size_t)E * Dm;
    const int* src = edge_index;
    const int* dst = edge_index + E;

    const int TB = 256;
    int XB = (N * 8 + TB - 1) / TB;
    int gE = (E + TB - 1) / TB;
    int gN128 = (N + TEB - 1) / TEB;
    int nTiles = (E + TEB - 1) / TEB;
    int gEdge = nTiles < 592 ? nTiles : 592;   // 4 blocks/SM x 148 SMs

    // Opt-in: k_edge static (~17.7KB) + dynamic (32KB) exceeds the 48KB
    // default combined limit — the attribute moves it to the large carveout.
    cudaFuncSetAttribute(k_edge, cudaFuncAttributeMaxDynamicSharedMemorySize, SMEM_EDGE_BYTES);
    cudaFuncSetAttribute(k_node, cudaFuncAttributeMaxDynamicSharedMemorySize, SMEM_NODE_BYTES);

    // launch 0: BN(x,u) + zero deg
    k_bn_xu<<<XB + 1, TB>>>((const float4*)node_feats, (const float4*)glob_feats,
                            (float4*)x, (float4*)u, ngam, nbet, ggam, gbet, N, B, XB);
    // launch 1: deg count + layer-0 hU
    k_deg_hu<<<gE + 1, TB>>>(dst, u, eW1, eb1, nW1, nb1, ebet, E, B);

    for (int l = 0; l < 3; l++) {
        const float* eW1l = eW1 + (size_t)l * 4 * Dm * Hm;   // (128,64)
        const float* nW1l = nW1 + (size_t)l * 3 * Dm * Hm;   // (96,64)
        const float* gW1l = gW1 + (size_t)l * 2 * Dm * Hm;   // (64,64)
        if (l > 0)
            k_hu<<<1, Hm>>>(u, eW1l, eb1 + l * Hm, nW1l, nb1 + l * Hm, B);
        k_pre<<<gN128, TEB>>>(x, batch, eW1l, N);            // launch 2 (l=0)
        k_edge<<<gEdge, TEB, SMEM_EDGE_BYTES>>>(src, dst,    // launch 3 (l=0) — profiled
                           (l == 0) ? edge_feats : e, e,
                           eW1l + 2 * Dm * Hm,               // rows 64..95 (e part)
                           eW2 + (size_t)l * Hm * Dm, eb2 + l * Dm,
                           (l == 0) ? egam : (const float*)nullptr, E, nTiles);
        k_node<<<gN128, TEB, SMEM_NODE_BYTES>>>(x, batch, nW1l,
                           nW2 + (size_t)l * Hm * Dm, nb2 + l * Dm, N);
        k_glob<<<B, 128>>>(u, x, batch, gW1l, gb1 + l * Hm,
                           gW2 + (size_t)l * Hm * Dm, gb2 + l * Dm, N);
    }
}

// round 15
// speedup vs baseline: 1.2144x; 1.0976x over previous
#include <cuda_runtime.h>
#include <cuda_fp16.h>
#include <cstdint>

#define Dm 32
#define Hm 64
#define NMAX 50000
#define BMAX 16
#define TEB 128
#define SEIN 132
#define SXT 132
#define SMEM_EDGE_BYTES (64 * 128 * 4)      // sHT [64][128] dominates; sEinT [32][132] aliases
#define SMEM_NODE_BYTES (64 * SXT * 4)      // sIn [64][132]; sHT [64][128] aliases

// ---------------- scratch ----------------------------------------------------
__device__ __align__(16) __half g_A [NMAX * Hm];   // fp16: A' = x@W1a + hU[batch]
__device__ __align__(16) __half g_Bp[NMAX * Hm];   // fp16: B  = x@W1b
__device__ __align__(16) float g_agg[NMAX * Dm];
__device__ __align__(16) float g_hU [BMAX * Hm];
__device__ __align__(16) float g_hUn[BMAX * Hm];
__device__ __align__(16) float g_xg [BMAX * Dm];   // segment-sum of x -> batch
__device__ float g_deg [NMAX];
__device__ float g_rdeg[NMAX];

// ---------------- packed f32x2 helpers ---------------------------------------
static __device__ __forceinline__ uint64_t ffma2(uint64_t a, uint64_t b, uint64_t c) {
    uint64_t d; asm("fma.rn.f32x2 %0, %1, %2, %3;" : "=l"(d) : "l"(a), "l"(b), "l"(c));
    return d;
}
static __device__ __forceinline__ uint64_t pack2(float lo, float hi) {
    uint64_t r; asm("mov.b64 %0, {%1, %2};" : "=l"(r) : "f"(lo), "f"(hi));
    return r;
}
static __device__ __forceinline__ float2 unpack2(uint64_t v) {
    float lo, hi; asm("mov.b64 {%0, %1}, %2;" : "=f"(lo), "=f"(hi) : "l"(v));
    float2 f; f.x = lo; f.y = hi; return f;
}
static __device__ __forceinline__ void red_add_v4(float* p, float a, float b, float c, float d) {
    asm volatile("red.global.add.v4.f32 [%0], {%1, %2, %3, %4};"
                 :: "l"(p), "f"(a), "f"(b), "f"(c), "f"(d) : "memory");
}

// ---------------- launch 0: BN for x and u (+ zero deg) ----------------------
__global__ void k_bn_xu(const float4* __restrict__ nf, const float4* __restrict__ gf,
                        float4* __restrict__ x, float4* __restrict__ u,
                        const float* __restrict__ ngam, const float* __restrict__ nbet,
                        const float* __restrict__ ggam, const float* __restrict__ gbet,
                        int N, int B, int XB) {
    const float r = rsqrtf(1.0f + 1e-5f);
    int bid = blockIdx.x, t = threadIdx.x;
    const float4* in; float4* out; const float* gm; const float* bt; int i4, lim;
    if (bid < XB) { i4 = bid * 256 + t; lim = N * 8; in = nf; out = x; gm = ngam; bt = nbet;
                    if (i4 < N) g_deg[i4] = 0.0f; }
    else          { i4 = t;             lim = B * 8; in = gf; out = u; gm = ggam; bt = gbet; }
    if (i4 >= lim) return;
    float4 v = in[i4];
    int c = (i4 * 4) & (Dm - 1);
    v.x = v.x * (gm[c + 0] * r) + bt[c + 0];
    v.y = v.y * (gm[c + 1] * r) + bt[c + 1];
    v.z = v.z * (gm[c + 2] * r) + bt[c + 2];
    v.w = v.w * (gm[c + 3] * r) + bt[c + 3];
    out[i4] = v;
}

// ---------------- hU/hUn body -------------------------------------------------
static __device__ __forceinline__ void hu_body(
    const float* __restrict__ u,
    const float* __restrict__ eW1, const float* __restrict__ eb1,
    const float* __restrict__ nW1, const float* __restrict__ nb1,
    const float* __restrict__ ebet, int B, int j)
{
    float c = 0.f;
    if (ebet) {            // layer 0: BN shift of e folded through W1c
#pragma unroll 4
        for (int k = 0; k < Dm; k++) c += ebet[k] * eW1[(2 * Dm + k) * Hm + j];
    }
    for (int b = 0; b < B; b++) {
        float hu = eb1[j] + c, hun = nb1[j];
#pragma unroll 4
        for (int k = 0; k < Dm; k++) {
            float uv = u[b * Dm + k];
            hu  += uv * eW1[(3 * Dm + k) * Hm + j];
            hun += uv * nW1[(2 * Dm + k) * Hm + j];
        }
        g_hU [b * Hm + j] = hu;
        g_hUn[b * Hm + j] = hun;
    }
}

// ---------------- launch 1: deg count + layer-0 hU ----------------------------
__global__ void k_deg_hu(const int* __restrict__ dst, const float* __restrict__ u,
                         const float* __restrict__ eW1, const float* __restrict__ eb1,
                         const float* __restrict__ nW1, const float* __restrict__ nb1,
                         const float* __restrict__ ebet, int E, int B) {
    if (blockIdx.x == gridDim.x - 1) {
        if (threadIdx.x < Hm) hu_body(u, eW1, eb1, nW1, nb1, ebet, B, threadIdx.x);
        return;
    }
    int i = blockIdx.x * blockDim.x + threadIdx.x;
    if (i < E) atomicAdd(&g_deg[dst[i]], 1.0f);
}

// layers 1,2: standalone hU
__global__ void k_hu(const float* __restrict__ u,
                     const float* __restrict__ eW1, const float* __restrict__ eb1,
                     const float* __restrict__ nW1, const float* __restrict__ nb1, int B) {
    if (threadIdx.x < Hm) hu_body(u, eW1, eb1, nW1, nb1, nullptr, B, threadIdx.x);
}

// ---------------- per-layer: A'/B precompute (tiled GEMM, fp16 out) ----------
__global__ void __launch_bounds__(128, 4) k_pre(const float* __restrict__ x,
                                                const int* __restrict__ batch,
                                                const float* __restrict__ eW1, int N) {
    __shared__ __align__(16) float sX[32 * SXT];
    __shared__ int sBt[TEB];
    int t = threadIdx.x;
    int n0 = blockIdx.x * TEB;
    sBt[t] = batch[min(n0 + t, N - 1)];
    if (n0 + t < N) g_rdeg[n0 + t] = 1.0f / fmaxf(g_deg[n0 + t], 1.0f);
    if (blockIdx.x == 0) ((float4*)g_xg)[t] = make_float4(0.f, 0.f, 0.f, 0.f);  // 128*4 = 512 floats
    {   // zero this block's agg region
        float4 z = make_float4(0.f, 0.f, 0.f, 0.f);
        float4* pz = (float4*)(g_agg + (size_t)n0 * Dm);
        int lim4 = min(TEB, N - n0) * 8;
        for (int i = t; i < lim4; i += TEB) pz[i] = z;
    }
    {   // stage x^T, quad swizzle
        int l8 = t & 7, g8 = t >> 3, k0 = l8 * 4;   // g8 in [0,16)
#pragma unroll 2
        for (int p = 0; p < 8; p++) {
            int nL = p * 16 + g8;
            int ngl = min(n0 + nL, N - 1);
            float4 v = __ldg((const float4*)(x + (size_t)ngl * Dm) + l8);
            int col = (((nL >> 2) ^ l8) << 2) + (nL & 3);
            sX[(k0 + 0) * SXT + col] = v.x;
            sX[(k0 + 1) * SXT + col] = v.y;
            sX[(k0 + 2) * SXT + col] = v.z;
            sX[(k0 + 3) * SXT + col] = v.w;
        }
    }
    __syncthreads();

    int jb = t & 7, nbk = t >> 3;       // nbk in [0,16)
    uint64_t acc[8][4];
#pragma unroll
    for (int g = 0; g < 2; g++) {       // g=0: A' (rows 0..31, hU bias); g=1: B (rows 32..63)
        const float* W = eW1 + g * Dm * Hm;
        __half* O = g ? g_Bp : g_A;
#pragma unroll
        for (int i = 0; i < 8; i++) {
            if (g == 0) {
                int bb = sBt[nbk * 8 + i];
                const ulonglong2* pb = (const ulonglong2*)(g_hU + bb * Hm + jb * 8);
                ulonglong2 b0 = __ldg(pb), b1 = __ldg(pb + 1);
                acc[i][0] = b0.x; acc[i][1] = b0.y; acc[i][2] = b1.x; acc[i][3] = b1.y;
            } else {
                acc[i][0] = acc[i][1] = acc[i][2] = acc[i][3] = 0ull;
            }
        }
#pragma unroll 4
        for (int k = 0; k < Dm; k++) {
            int sw = k >> 2;
            const float4* pe = (const float4*)(sX + k * SXT);
            float4 ea = pe[(nbk * 2) ^ sw];
            float4 eb = pe[(nbk * 2 + 1) ^ sw];
            ulonglong2 wA = __ldg((const ulonglong2*)(W + k * Hm + jb * 8));
            ulonglong2 wB = __ldg((const ulonglong2*)(W + k * Hm + jb * 8 + 4));
            float ev[8] = {ea.x, ea.y, ea.z, ea.w, eb.x, eb.y, eb.z, eb.w};
#pragma unroll
            for (int i = 0; i < 8; i++) {
                uint64_t ed = pack2(ev[i], ev[i]);
                acc[i][0] = ffma2(ed, wA.x, acc[i][0]);
                acc[i][1] = ffma2(ed, wA.y, acc[i][1]);
                acc[i][2] = ffma2(ed, wB.x, acc[i][2]);
                acc[i][3] = ffma2(ed, wB.y, acc[i][3]);
            }
        }
#pragma unroll
        for (int i = 0; i < 8; i++) {
            int n = n0 + nbk * 8 + i;
            if (n < N) {
                float2 f0 = unpack2(acc[i][0]), f1 = unpack2(acc[i][1]);
                float2 f2 = unpack2(acc[i][2]), f3 = unpack2(acc[i][3]);
                __half2 hs[4];
                hs[0] = __floats2half2_rn(f0.x, f0.y);
                hs[1] = __floats2half2_rn(f1.x, f1.y);
                hs[2] = __floats2half2_rn(f2.x, f2.y);
                hs[3] = __floats2half2_rn(f3.x, f3.y);
                *(uint4*)(O + (size_t)n * Hm + jb * 8) = *(uint4*)hs;
            }
        }
    }
}

// ---------------- per-layer: edge MLP — persistent tiles, fp16 bias gather ---
__global__ void __launch_bounds__(128, 4) k_edge(
    const int* __restrict__ src, const int* __restrict__ dst,
    const float* __restrict__ ein, float* __restrict__ eout,
    const float* __restrict__ W1c, const float* __restrict__ W2,
    const float* __restrict__ b2, const float* __restrict__ escale,
    int E, int nTiles)
{
    extern __shared__ float smem[];
    float* sEinT = smem;                  // [32][132], alive through GEMM1
    float* sHT   = smem;                  // [64][128] overlay
    __shared__ __align__(16) float sW1[Dm * Hm];   // 8KB
    __shared__ __align__(16) float sW2[Hm * Dm];   // 8KB
    __shared__ __align__(16) float sB2[Dm];
    __shared__ int sS[TEB], sD[TEB];
    __shared__ float sSc[Dm];
    int t = threadIdx.x;
    if (t < Dm) {
        sSc[t] = escale ? escale[t] * rsqrtf(1.0f + 1e-5f) : 1.0f;
        sB2[t] = b2[t];
    }
    for (int i = t; i < Dm * Hm; i += TEB) { sW1[i] = W1c[i]; sW2[i] = W2[i]; }
    int jb = t & 7, ebk = t >> 3;         // ebk in [0,16)
    int l8 = t & 7, g8 = t >> 3;

    // prefetch first tile's src/dst
    int pS, pD;
    {
        int ei0 = min(blockIdx.x * TEB + t, E - 1);
        pS = src[ei0]; pD = dst[ei0];
    }

    for (int tile = blockIdx.x; tile < nTiles; tile += gridDim.x) {
        int e0 = tile * TEB;
        __syncthreads();                  // prev tile's sHT/sD reads done; weights visible (1st iter)
        sS[t] = pS; sD[t] = pD;

        // ---- stage Ein transposed, quad swizzle, BN scale fold ----
        {
            int k0 = l8 * 4;
            float s0 = sSc[k0], s1 = sSc[k0 + 1], s2 = sSc[k0 + 2], s3 = sSc[k0 + 3];
#pragma unroll 2
            for (int p = 0; p < 8; p++) {
                int eL = p * 16 + g8;
                int eg = min(e0 + eL, E - 1);
                float4 v = __ldg((const float4*)(ein + (size_t)eg * Dm) + l8);
                int col = (((eL >> 2) ^ l8) << 2) + (eL & 3);
                sEinT[(k0 + 0) * SEIN + col] = v.x * s0;
                sEinT[(k0 + 1) * SEIN + col] = v.y * s1;
                sEinT[(k0 + 2) * SEIN + col] = v.z * s2;
                sEinT[(k0 + 3) * SEIN + col] = v.w * s3;
            }
        }
        __syncthreads();                  // sS/sD + sEinT visible

        // ---- prefetch next tile's src/dst (overlaps GEMM1/2) ----
        {
            int tn = tile + gridDim.x;
            if (tn < nTiles) {
                int eiN = min(tn * TEB + t, E - 1);
                pS = src[eiN]; pD = dst[eiN];
            }
        }

        // ---- direct bias init: acc = A'[src] + B[dst]  (fp16 gathers) ----
        uint64_t acc[8][4];
#pragma unroll
        for (int i = 0; i < 8; i++) {
            int eL = ebk * 8 + i;
            uint4 ua = __ldg((const uint4*)(g_A  + (size_t)sS[eL] * Hm + jb * 8));
            uint4 ub = __ldg((const uint4*)(g_Bp + (size_t)sD[eL] * Hm + jb * 8));
            const __half2* ha = (const __half2*)&ua;
            const __half2* hb = (const __half2*)&ub;
#pragma unroll
            for (int q = 0; q < 4; q++) {
                float2 fa = __half22float2(ha[q]);
                float2 fb = __half22float2(hb[q]);
                acc[i][q] = pack2(fa.x + fb.x, fa.y + fb.y);
            }
        }

        // ---- GEMM1: H[128x64] = EinT^T @ W1c + bias (weights from smem) ----
#pragma unroll 4
        for (int k = 0; k < Dm; k++) {
            int sw = k >> 2;
            const float4* pe = (const float4*)(sEinT + k * SEIN);
            float4 ea = pe[(ebk * 2) ^ sw];
            float4 eb = pe[(ebk * 2 + 1) ^ sw];
            const ulonglong2* pw = (const ulonglong2*)(sW1 + k * Hm + jb * 8);
            ulonglong2 wA = pw[0], wB = pw[1];
            float ev[8] = {ea.x, ea.y, ea.z, ea.w, eb.x, eb.y, eb.z, eb.w};
#pragma unroll
            for (int i = 0; i < 8; i++) {
                uint64_t ed = pack2(ev[i], ev[i]);
                acc[i][0] = ffma2(ed, wA.x, acc[i][0]);
                acc[i][1] = ffma2(ed, wA.y, acc[i][1]);
                acc[i][2] = ffma2(ed, wB.x, acc[i][2]);
                acc[i][3] = ffma2(ed, wB.y, acc[i][3]);
            }
        }
        __syncthreads();                  // sEinT dead; overlay sHT

        // ---- relu + store H^T [64][128], quad swizzle q ^ jb ----
#pragma unroll
        for (int jj = 0; jj < 8; jj++) {
            int j = jb * 8 + jj;
            float f[8];
#pragma unroll
            for (int i = 0; i < 8; i++) {
                float2 v = unpack2(acc[i][jj >> 1]);
                f[i] = fmaxf((jj & 1) ? v.y : v.x, 0.f);
            }
            *(float4*)(sHT + j * 128 + (((ebk * 2)     ^ jb) << 2)) = make_float4(f[0], f[1], f[2], f[3]);
            *(float4*)(sHT + j * 128 + (((ebk * 2 + 1) ^ jb) << 2)) = make_float4(f[4], f[5], f[6], f[7]);
        }
        __syncthreads();

        // ---- GEMM2: OUT[128x32] = relu(H) @ W2 + b2 (weights from smem) ----
        uint64_t out[8][2];
        {
            ulonglong2 bb = *(const ulonglong2*)(sB2 + jb * 4);
#pragma unroll
            for (int i = 0; i < 8; i++) { out[i][0] = bb.x; out[i][1] = bb.y; }
        }
#pragma unroll 4
        for (int k = 0; k < Hm; k++) {
            int sw = (k >> 3) & 7;
            const float4* ph = (const float4*)(sHT + k * 128);
            float4 h0 = ph[(ebk * 2) ^ sw];
            float4 h1 = ph[(ebk * 2 + 1) ^ sw];
            ulonglong2 w = *(const ulonglong2*)(sW2 + k * Dm + jb * 4);
            float hv[8] = {h0.x, h0.y, h0.z, h0.w, h1.x, h1.y, h1.z, h1.w};
#pragma unroll
            for (int i = 0; i < 8; i++) {
                uint64_t hd = pack2(hv[i], hv[i]);
                out[i][0] = ffma2(hd, w.x, out[i][0]);
                out[i][1] = ffma2(hd, w.y, out[i][1]);
            }
        }
        // ---- epilogue: write e + fused RED into agg ----
#pragma unroll
        for (int i = 0; i < 8; i++) {
            int eL = ebk * 8 + i, eg = e0 + eL;
            if (eg < E) {
                float2 a = unpack2(out[i][0]); float2 b = unpack2(out[i][1]);
                *(float4*)(eout + (size_t)eg * Dm + jb * 4) = make_float4(a.x, a.y, b.x, b.y);
                red_add_v4(g_agg + (size_t)sD[eL] * Dm + jb * 4, a.x, a.y, b.x, b.y);
            }
        }
    }
}

// ---------------- per-layer: node MLP — 128-thread tiles + fused xg RED ------
__global__ void __launch_bounds__(128, 4) k_node(
    float* __restrict__ x, const int* __restrict__ batch,
    const float* __restrict__ W1, const float* __restrict__ W2, const float* __restrict__ b2,
    int N)
{
    extern __shared__ float smem[];
    float* sIn = smem;     // [64][132]: rows 0..31 = x^T, rows 32..63 = (agg*rd)^T
    float* sHT = smem;     // overlay after GEMM1: [64][128]
    __shared__ int sBt[TEB];
    int t = threadIdx.x;
    int n0 = blockIdx.x * TEB;
    sBt[t] = batch[min(n0 + t, N - 1)];
    {
        int l8 = t & 7, g8 = t >> 3, k0 = l8 * 4;
#pragma unroll 2
        for (int p = 0; p < 8; p++) {
            int nL = p * 16 + g8;
            int ngl = min(n0 + nL, N - 1);
            float4 vx = __ldg((const float4*)(x + (size_t)ngl * Dm) + l8);
            float rd = g_rdeg[ngl];
            float4 va = __ldg((const float4*)(g_agg + (size_t)ngl * Dm) + l8);
            int col = (((nL >> 2) ^ l8) << 2) + (nL & 3);
            sIn[(k0 + 0) * SXT + col] = vx.x;
            sIn[(k0 + 1) * SXT + col] = vx.y;
            sIn[(k0 + 2) * SXT + col] = vx.z;
            sIn[(k0 + 3) * SXT + col] = vx.w;
            sIn[(Dm + k0 + 0) * SXT + col] = va.x * rd;
            sIn[(Dm + k0 + 1) * SXT + col] = va.y * rd;
            sIn[(Dm + k0 + 2) * SXT + col] = va.z * rd;
            sIn[(Dm + k0 + 3) * SXT + col] = va.w * rd;
        }
    }
    __syncthreads();

    // ---- GEMM1: H[128x64] = In^T @ W1(rows 0..63) + hUn[batch] ----
    int jb = t & 7, nbk = t >> 3;
    uint64_t acc[8][4];
#pragma unroll
    for (int i = 0; i < 8; i++) {
        int bb = sBt[nbk * 8 + i];
        const ulonglong2* pb = (const ulonglong2*)(g_hUn + bb * Hm + jb * 8);
        ulonglong2 b0 = __ldg(pb), b1 = __ldg(pb + 1);
        acc[i][0] = b0.x; acc[i][1] = b0.y; acc[i][2] = b1.x; acc[i][3] = b1.y;
    }
#pragma unroll 4
    for (int k = 0; k < 2 * Dm; k++) {
        int sw = (k >> 2) & 7;
        const float4* pe = (const float4*)(sIn + k * SXT);
        float4 ea = pe[(nbk * 2) ^ sw];
        float4 eb = pe[(nbk * 2 + 1) ^ sw];
        ulonglong2 wA = __ldg((const ulonglong2*)(W1 + k * Hm + jb * 8));
        ulonglong2 wB = __ldg((const ulonglong2*)(W1 + k * Hm + jb * 8 + 4));
        float ev[8] = {ea.x, ea.y, ea.z, ea.w, eb.x, eb.y, eb.z, eb.w};
#pragma unroll
        for (int i = 0; i < 8; i++) {
            uint64_t ed = pack2(ev[i], ev[i]);
            acc[i][0] = ffma2(ed, wA.x, acc[i][0]);
            acc[i][1] = ffma2(ed, wA.y, acc[i][1]);
            acc[i][2] = ffma2(ed, wB.x, acc[i][2]);
            acc[i][3] = ffma2(ed, wB.y, acc[i][3]);
        }
    }
    __syncthreads();   // all reads of sIn complete before HT overlay

#pragma unroll
    for (int jj = 0; jj < 8; jj++) {
        int j = jb * 8 + jj;
        float f[8];
#pragma unroll
        for (int i = 0; i < 8; i++) {
            float2 v = unpack2(acc[i][jj >> 1]);
            f[i] = fmaxf((jj & 1) ? v.y : v.x, 0.f);
        }
        *(float4*)(sHT + j * 128 + (((nbk * 2)     ^ jb) << 2)) = make_float4(f[0], f[1], f[2], f[3]);
        *(float4*)(sHT + j * 128 + (((nbk * 2 + 1) ^ jb) << 2)) = make_float4(f[4], f[5], f[6], f[7]);
    }
    __syncthreads();

    // ---- GEMM2: OUT[128x32] = relu(H) @ W2 + b2 ----
    uint64_t out[8][2];
    {
        ulonglong2 bb = __ldg((const ulonglong2*)(b2 + jb * 4));
#pragma unroll
        for (int i = 0; i < 8; i++) { out[i][0] = bb.x; out[i][1] = bb.y; }
    }
#pragma unroll 4
    for (int k = 0; k < Hm; k++) {
        int sw = (k >> 3) & 7;
        const float4* ph = (const float4*)(sHT + k * 128);
        float4 h0 = ph[(nbk * 2) ^ sw];
        float4 h1 = ph[(nbk * 2 + 1) ^ sw];
        ulonglong2 w = __ldg((const ulonglong2*)(W2 + k * Dm + jb * 4));
        float hv[8] = {h0.x, h0.y, h0.z, h0.w, h1.x, h1.y, h1.z, h1.w};
#pragma unroll
        for (int i = 0; i < 8; i++) {
            uint64_t hd = pack2(hv[i], hv[i]);
            out[i][0] = ffma2(hd, w.x, out[i][0]);
            out[i][1] = ffma2(hd, w.y, out[i][1]);
        }
    }
    // ---- epilogue: write x + run-length-grouped RED into g_xg ----
    {
        float4 s = make_float4(0.f, 0.f, 0.f, 0.f);
        int curb = -1;
#pragma unroll
        for (int i = 0; i < 8; i++) {
            int n = n0 + nbk * 8 + i;
            if (n < N) {
                float2 a = unpack2(out[i][0]); float2 b = unpack2(out[i][1]);
                *(float4*)(x + (size_t)n * Dm + jb * 4) = make_float4(a.x, a.y, b.x, b.y);
                int bb = sBt[nbk * 8 + i];
                if (bb != curb) {
                    if (curb >= 0) red_add_v4(g_xg + curb * Dm + jb * 4, s.x, s.y, s.z, s.w);
                    curb = bb; s = make_float4(0.f, 0.f, 0.f, 0.f);
                }
                s.x += a.x; s.y += a.y; s.z += b.x; s.w += b.y;
            }
        }
        if (curb >= 0) red_add_v4(g_xg + curb * Dm + jb * 4, s.x, s.y, s.z, s.w);
    }
}

// ---------------- per-layer: global MLP (reads precomputed g_xg) -------------
static __device__ __forceinline__ int lowerb(const int* __restrict__ a, int n, int v) {
    int lo = 0, hi = n;
    while (lo < hi) { int m = (lo + hi) >> 1; if (a[m] < v) lo = m + 1; else hi = m; }
    return lo;
}
__global__ void k_glob(float* __restrict__ u, const int* __restrict__ batch,
                       const float* __restrict__ W1, const float* __restrict__ b1,
                       const float* __restrict__ W2, const float* __restrict__ b2, int N) {
    int b = blockIdx.x, t = threadIdx.x;       // 128 threads
    __shared__ int sLo, sHi;
    __shared__ float su[2 * Dm];
    __shared__ float sh[Hm];
    if (t == 0) { sLo = lowerb(batch, N, b); sHi = lowerb(batch, N, b + 1); }
    __syncthreads();
    float cnt = fmaxf((float)(sHi - sLo), 1.0f);
    if (t < Dm) su[t] = u[b * Dm + t];
    else if (t < 2 * Dm) su[t] = g_xg[b * Dm + (t - Dm)] / cnt;
    __syncthreads();
    if (t < Hm) {
        float h = b1[t];
#pragma unroll 4
        for (int k = 0; k < 2 * Dm; k++) h += su[k] * W1[k * Hm + t];
        sh[t] = fmaxf(h, 0.f);
    }
    __syncthreads();
    if (t < Dm) {
        float o = b2[t];
#pragma unroll 4
        for (int k = 0; k < Hm; k++) o += sh[k] * W2[k * Dm + t];
        u[b * Dm + t] = o;
    }
}

// ---------------- launch -----------------------------------------------------
extern "C" void kernel_launch(void* const* d_in, const int* in_sizes, int n_in,
                              void* d_out, int out_size) {
    const float* node_feats = (const float*)d_in[0];
    const int*   edge_index = (const int*)  d_in[1];
    const float* edge_feats = (const float*)d_in[2];
    const float* glob_feats = (const float*)d_in[3];
    const int*   batch      = (const int*)  d_in[4];
    const float* ngam = (const float*)d_in[5];
    const float* nbet = (const float*)d_in[6];
    const float* egam = (const float*)d_in[7];
    const float* ebet = (const float*)d_in[8];
    const float* ggam = (const float*)d_in[9];
    const float* gbet = (const float*)d_in[10];
    const float* eW1 = (const float*)d_in[11];
    const float* eb1 = (const float*)d_in[12];
    const float* eW2 = (const float*)d_in[13];
    const float* eb2 = (const float*)d_in[14];
    const float* nW1 = (const float*)d_in[15];
    const float* nb1 = (const float*)d_in[16];
    const float* nW2 = (const float*)d_in[17];
    const float* nb2 = (const float*)d_in[18];
    const float* gW1 = (const float*)d_in[19];
    const float* gb1 = (const float*)d_in[20];
    const float* gW2 = (const float*)d_in[21];
    const float* gb2 = (const float*)d_in[22];

    const int N = in_sizes[0] / Dm;
    const int E = in_sizes[2] / Dm;
    const int B = in_sizes[3] / Dm;

    float* x = (float*)d_out;
    float* e = x + (size_t)N * Dm;
    float* u = e + (size_t)E * Dm;
    const int* src = edge_index;
    const int* dst = edge_index + E;

    const int TB = 256;
    int XB = (N * 8 + TB - 1) / TB;
    int gE = (E + TB - 1) / TB;
    int gN128 = (N + TEB - 1) / TEB;
    int nTiles = (E + TEB - 1) / TEB;
    int gEdge = nTiles < 592 ? nTiles : 592;   // 4 blocks/SM x 148 SMs

    // Opt-in: k_edge static (~17.7KB) + dynamic (32KB) exceeds the 48KB
    // default combined limit — the attribute moves it to the large carveout.
    cudaFuncSetAttribute(k_edge, cudaFuncAttributeMaxDynamicSharedMemorySize, SMEM_EDGE_BYTES);
    cudaFuncSetAttribute(k_node, cudaFuncAttributeMaxDynamicSharedMemorySize, SMEM_NODE_BYTES);

    // launch 0: BN(x,u) + zero deg
    k_bn_xu<<<XB + 1, TB>>>((const float4*)node_feats, (const float4*)glob_feats,
                            (float4*)x, (float4*)u, ngam, nbet, ggam, gbet, N, B, XB);
    // launch 1: deg count + layer-0 hU
    k_deg_hu<<<gE + 1, TB>>>(dst, u, eW1, eb1, nW1, nb1, ebet, E, B);

    for (int l = 0; l < 3; l++) {
        const float* eW1l = eW1 + (size_t)l * 4 * Dm * Hm;   // (128,64)
        const float* nW1l = nW1 + (size_t)l * 3 * Dm * Hm;   // (96,64)
        const float* gW1l = gW1 + (size_t)l * 2 * Dm * Hm;   // (64,64)
        if (l > 0)
            k_hu<<<1, Hm>>>(u, eW1l, eb1 + l * Hm, nW1l, nb1 + l * Hm, B);
        k_pre<<<gN128, TEB>>>(x, batch, eW1l, N);            // launch 2 (l=0)
        k_edge<<<gEdge, TEB, SMEM_EDGE_BYTES>>>(src, dst,    // launch 3 (l=0) — profiled
                           (l == 0) ? edge_feats : e, e,
                           eW1l + 2 * Dm * Hm,               // rows 64..95 (e part)
                           eW2 + (size_t)l * Hm * Dm, eb2 + l * Dm,
                           (l == 0) ? egam : (const float*)nullptr, E, nTiles);
        k_node<<<gN128, TEB, SMEM_NODE_BYTES>>>(x, batch, nW1l,
                           nW2 + (size_t)l * Hm * Dm, nb2 + l * Dm, N);
        k_glob<<<B, 128>>>(u, batch, gW1l, gb1 + l * Hm,
                           gW2 + (size_t)l * Hm * Dm, gb2 + l * Dm, N);
    }
}

// round 16
// speedup vs baseline: 1.2633x; 1.0402x over previous
#include <cuda_runtime.h>
#include <cuda_fp16.h>
#include <cstdint>

#define Dm 32
#define Hm 64
#define NMAX 50000
#define EMAX 800000
#define BMAX 16
#define TEB 128
#define SEIN 132
#define SXT 132
#define SMEM_EDGE_BYTES (64 * 128 * 4)      // sHT [64][128] dominates; sEinT [32][132] aliases
#define SMEM_NODE_BYTES (64 * SXT * 4)      // sIn [64][132]; sHT [64][128] aliases

// ---------------- scratch ----------------------------------------------------
__device__ __align__(16) __half g_A [NMAX * Hm];   // fp16: A' = x@W1a + hU[batch]
__device__ __align__(16) __half g_Bp[NMAX * Hm];   // fp16: B  = x@W1b
__device__ __align__(16) __half g_e16[(size_t)EMAX * Dm];  // fp16 intermediate e
__device__ __align__(16) float g_agg[NMAX * Dm];
__device__ __align__(16) float g_hU [BMAX * Hm];
__device__ __align__(16) float g_hUn[BMAX * Hm];
__device__ __align__(16) float g_xg [BMAX * Dm];   // segment-sum of x -> batch
__device__ float g_deg [NMAX];
__device__ float g_rdeg[NMAX];

// ---------------- packed f32x2 helpers ---------------------------------------
static __device__ __forceinline__ uint64_t ffma2(uint64_t a, uint64_t b, uint64_t c) {
    uint64_t d; asm("fma.rn.f32x2 %0, %1, %2, %3;" : "=l"(d) : "l"(a), "l"(b), "l"(c));
    return d;
}
static __device__ __forceinline__ uint64_t pack2(float lo, float hi) {
    uint64_t r; asm("mov.b64 %0, {%1, %2};" : "=l"(r) : "f"(lo), "f"(hi));
    return r;
}
static __device__ __forceinline__ float2 unpack2(uint64_t v) {
    float lo, hi; asm("mov.b64 {%0, %1}, %2;" : "=f"(lo), "=f"(hi) : "l"(v));
    float2 f; f.x = lo; f.y = hi; return f;
}
static __device__ __forceinline__ void red_add_v4(float* p, float a, float b, float c, float d) {
    asm volatile("red.global.add.v4.f32 [%0], {%1, %2, %3, %4};"
                 :: "l"(p), "f"(a), "f"(b), "f"(c), "f"(d) : "memory");
}

// ---------------- launch 0: BN for x and u (+ zero deg) ----------------------
__global__ void k_bn_xu(const float4* __restrict__ nf, const float4* __restrict__ gf,
                        float4* __restrict__ x, float4* __restrict__ u,
                        const float* __restrict__ ngam, const float* __restrict__ nbet,
                        const float* __restrict__ ggam, const float* __restrict__ gbet,
                        int N, int B, int XB) {
    const float r = rsqrtf(1.0f + 1e-5f);
    int bid = blockIdx.x, t = threadIdx.x;
    const float4* in; float4* out; const float* gm; const float* bt; int i4, lim;
    if (bid < XB) { i4 = bid * 256 + t; lim = N * 8; in = nf; out = x; gm = ngam; bt = nbet;
                    if (i4 < N) g_deg[i4] = 0.0f; }
    else          { i4 = t;             lim = B * 8; in = gf; out = u; gm = ggam; bt = gbet; }
    if (i4 >= lim) return;
    float4 v = in[i4];
    int c = (i4 * 4) & (Dm - 1);
    v.x = v.x * (gm[c + 0] * r) + bt[c + 0];
    v.y = v.y * (gm[c + 1] * r) + bt[c + 1];
    v.z = v.z * (gm[c + 2] * r) + bt[c + 2];
    v.w = v.w * (gm[c + 3] * r) + bt[c + 3];
    out[i4] = v;
}

// ---------------- hU/hUn body (layer 0 only) ----------------------------------
static __device__ __forceinline__ void hu_body(
    const float* __restrict__ u,
    const float* __restrict__ eW1, const float* __restrict__ eb1,
    const float* __restrict__ nW1, const float* __restrict__ nb1,
    const float* __restrict__ ebet, int B, int j)
{
    float c = 0.f;
    if (ebet) {            // layer 0: BN shift of e folded through W1c
#pragma unroll 4
        for (int k = 0; k < Dm; k++) c += ebet[k] * eW1[(2 * Dm + k) * Hm + j];
    }
    for (int b = 0; b < B; b++) {
        float hu = eb1[j] + c, hun = nb1[j];
#pragma unroll 4
        for (int k = 0; k < Dm; k++) {
            float uv = u[b * Dm + k];
            hu  += uv * eW1[(3 * Dm + k) * Hm + j];
            hun += uv * nW1[(2 * Dm + k) * Hm + j];
        }
        g_hU [b * Hm + j] = hu;
        g_hUn[b * Hm + j] = hun;
    }
}

// ---------------- launch 1: deg count + layer-0 hU ----------------------------
__global__ void k_deg_hu(const int* __restrict__ dst, const float* __restrict__ u,
                         const float* __restrict__ eW1, const float* __restrict__ eb1,
                         const float* __restrict__ nW1, const float* __restrict__ nb1,
                         const float* __restrict__ ebet, int E, int B) {
    if (blockIdx.x == gridDim.x - 1) {
        if (threadIdx.x < Hm) hu_body(u, eW1, eb1, nW1, nb1, ebet, B, threadIdx.x);
        return;
    }
    int i = blockIdx.x * blockDim.x + threadIdx.x;
    if (i < E) atomicAdd(&g_deg[dst[i]], 1.0f);
}

// ---------------- per-layer: A'/B precompute (tiled GEMM, fp16 out) ----------
__global__ void __launch_bounds__(128, 4) k_pre(const float* __restrict__ x,
                                                const int* __restrict__ batch,
                                                const float* __restrict__ eW1, int N) {
    __shared__ __align__(16) float sX[32 * SXT];
    __shared__ int sBt[TEB];
    int t = threadIdx.x;
    int n0 = blockIdx.x * TEB;
    sBt[t] = batch[min(n0 + t, N - 1)];
    if (n0 + t < N) g_rdeg[n0 + t] = 1.0f / fmaxf(g_deg[n0 + t], 1.0f);
    if (blockIdx.x == 0) ((float4*)g_xg)[t] = make_float4(0.f, 0.f, 0.f, 0.f);
    {   // zero this block's agg region
        float4 z = make_float4(0.f, 0.f, 0.f, 0.f);
        float4* pz = (float4*)(g_agg + (size_t)n0 * Dm);
        int lim4 = min(TEB, N - n0) * 8;
        for (int i = t; i < lim4; i += TEB) pz[i] = z;
    }
    {   // stage x^T, quad swizzle
        int l8 = t & 7, g8 = t >> 3, k0 = l8 * 4;
#pragma unroll 2
        for (int p = 0; p < 8; p++) {
            int nL = p * 16 + g8;
            int ngl = min(n0 + nL, N - 1);
            float4 v = __ldg((const float4*)(x + (size_t)ngl * Dm) + l8);
            int col = (((nL >> 2) ^ l8) << 2) + (nL & 3);
            sX[(k0 + 0) * SXT + col] = v.x;
            sX[(k0 + 1) * SXT + col] = v.y;
            sX[(k0 + 2) * SXT + col] = v.z;
            sX[(k0 + 3) * SXT + col] = v.w;
        }
    }
    __syncthreads();

    int jb = t & 7, nbk = t >> 3;
    uint64_t acc[8][4];
#pragma unroll
    for (int g = 0; g < 2; g++) {       // g=0: A' (rows 0..31, hU bias); g=1: B (rows 32..63)
        const float* W = eW1 + g * Dm * Hm;
        __half* O = g ? g_Bp : g_A;
#pragma unroll
        for (int i = 0; i < 8; i++) {
            if (g == 0) {
                int bb = sBt[nbk * 8 + i];
                const ulonglong2* pb = (const ulonglong2*)(g_hU + bb * Hm + jb * 8);
                ulonglong2 b0 = __ldg(pb), b1 = __ldg(pb + 1);
                acc[i][0] = b0.x; acc[i][1] = b0.y; acc[i][2] = b1.x; acc[i][3] = b1.y;
            } else {
                acc[i][0] = acc[i][1] = acc[i][2] = acc[i][3] = 0ull;
            }
        }
#pragma unroll 4
        for (int k = 0; k < Dm; k++) {
            int sw = k >> 2;
            const float4* pe = (const float4*)(sX + k * SXT);
            float4 ea = pe[(nbk * 2) ^ sw];
            float4 eb = pe[(nbk * 2 + 1) ^ sw];
            ulonglong2 wA = __ldg((const ulonglong2*)(W + k * Hm + jb * 8));
            ulonglong2 wB = __ldg((const ulonglong2*)(W + k * Hm + jb * 8 + 4));
            float ev[8] = {ea.x, ea.y, ea.z, ea.w, eb.x, eb.y, eb.z, eb.w};
#pragma unroll
            for (int i = 0; i < 8; i++) {
                uint64_t ed = pack2(ev[i], ev[i]);
                acc[i][0] = ffma2(ed, wA.x, acc[i][0]);
                acc[i][1] = ffma2(ed, wA.y, acc[i][1]);
                acc[i][2] = ffma2(ed, wB.x, acc[i][2]);
                acc[i][3] = ffma2(ed, wB.y, acc[i][3]);
            }
        }
#pragma unroll
        for (int i = 0; i < 8; i++) {
            int n = n0 + nbk * 8 + i;
            if (n < N) {
                float2 f0 = unpack2(acc[i][0]), f1 = unpack2(acc[i][1]);
                float2 f2 = unpack2(acc[i][2]), f3 = unpack2(acc[i][3]);
                __half2 hs[4];
                hs[0] = __floats2half2_rn(f0.x, f0.y);
                hs[1] = __floats2half2_rn(f1.x, f1.y);
                hs[2] = __floats2half2_rn(f2.x, f2.y);
                hs[3] = __floats2half2_rn(f3.x, f3.y);
                *(uint4*)(O + (size_t)n * Hm + jb * 8) = *(uint4*)hs;
            }
        }
    }
}

// ---------------- per-layer: edge MLP — persistent tiles, fp16 e path --------
__global__ void __launch_bounds__(128, 4) k_edge(
    const int* __restrict__ src, const int* __restrict__ dst,
    const float* __restrict__ ein,   // fp32 input (layer 0) or nullptr -> read g_e16
    float* __restrict__ eoutf,       // fp32 output (last layer) or nullptr -> write g_e16
    const float* __restrict__ W1c, const float* __restrict__ W2,
    const float* __restrict__ b2, const float* __restrict__ escale,
    int E, int nTiles)
{
    extern __shared__ float smem[];
    float* sEinT = smem;                  // [32][132], alive through GEMM1
    float* sHT   = smem;                  // [64][128] overlay
    __shared__ __align__(16) float sW1[Dm * Hm];   // 8KB
    __shared__ __align__(16) float sW2[Hm * Dm];   // 8KB
    __shared__ __align__(16) float sB2[Dm];
    __shared__ int sS[TEB], sD[TEB];
    __shared__ float sSc[Dm];
    int t = threadIdx.x;
    if (t < Dm) {
        sSc[t] = escale ? escale[t] * rsqrtf(1.0f + 1e-5f) : 1.0f;
        sB2[t] = b2[t];
    }
    for (int i = t; i < Dm * Hm; i += TEB) { sW1[i] = W1c[i]; sW2[i] = W2[i]; }
    int jb = t & 7, ebk = t >> 3;
    int l8 = t & 7, g8 = t >> 3;

    // prefetch first tile's src/dst
    int pS, pD;
    {
        int ei0 = min(blockIdx.x * TEB + t, E - 1);
        pS = src[ei0]; pD = dst[ei0];
    }

    for (int tile = blockIdx.x; tile < nTiles; tile += gridDim.x) {
        int e0 = tile * TEB;
        __syncthreads();                  // prev tile's sHT/sD reads done; weights visible (1st iter)
        sS[t] = pS; sD[t] = pD;

        // ---- stage Ein transposed, quad swizzle ----
        {
            int k0 = l8 * 4;
            if (ein) {                    // fp32 input, BN scale fold (layer 0)
                float s0 = sSc[k0], s1 = sSc[k0 + 1], s2 = sSc[k0 + 2], s3 = sSc[k0 + 3];
#pragma unroll 2
                for (int p = 0; p < 8; p++) {
                    int eL = p * 16 + g8;
                    int eg = min(e0 + eL, E - 1);
                    float4 v = __ldg((const float4*)(ein + (size_t)eg * Dm) + l8);
                    int col = (((eL >> 2) ^ l8) << 2) + (eL & 3);
                    sEinT[(k0 + 0) * SEIN + col] = v.x * s0;
                    sEinT[(k0 + 1) * SEIN + col] = v.y * s1;
                    sEinT[(k0 + 2) * SEIN + col] = v.z * s2;
                    sEinT[(k0 + 3) * SEIN + col] = v.w * s3;
                }
            } else {                      // fp16 intermediate e
#pragma unroll 2
                for (int p = 0; p < 8; p++) {
                    int eL = p * 16 + g8;
                    int eg = min(e0 + eL, E - 1);
                    uint2 hv = __ldg((const uint2*)(g_e16 + (size_t)eg * Dm) + l8);
                    const __half2* hp = (const __half2*)&hv;
                    float2 f0 = __half22float2(hp[0]);
                    float2 f1 = __half22float2(hp[1]);
                    int col = (((eL >> 2) ^ l8) << 2) + (eL & 3);
                    sEinT[(k0 + 0) * SEIN + col] = f0.x;
                    sEinT[(k0 + 1) * SEIN + col] = f0.y;
                    sEinT[(k0 + 2) * SEIN + col] = f1.x;
                    sEinT[(k0 + 3) * SEIN + col] = f1.y;
                }
            }
        }
        __syncthreads();                  // sS/sD + sEinT visible

        // ---- prefetch next tile's src/dst (overlaps GEMM1/2) ----
        {
            int tn = tile + gridDim.x;
            if (tn < nTiles) {
                int eiN = min(tn * TEB + t, E - 1);
                pS = src[eiN]; pD = dst[eiN];
            }
        }

        // ---- direct bias init: acc = A'[src] + B[dst]  (fp16 gathers) ----
        uint64_t acc[8][4];
#pragma unroll
        for (int i = 0; i < 8; i++) {
            int eL = ebk * 8 + i;
            uint4 ua = __ldg((const uint4*)(g_A  + (size_t)sS[eL] * Hm + jb * 8));
            uint4 ub = __ldg((const uint4*)(g_Bp + (size_t)sD[eL] * Hm + jb * 8));
            const __half2* ha = (const __half2*)&ua;
            const __half2* hb = (const __half2*)&ub;
#pragma unroll
            for (int q = 0; q < 4; q++) {
                float2 fa = __half22float2(ha[q]);
                float2 fb = __half22float2(hb[q]);
                acc[i][q] = pack2(fa.x + fb.x, fa.y + fb.y);
            }
        }

        // ---- GEMM1: H[128x64] = EinT^T @ W1c + bias (weights from smem) ----
#pragma unroll 4
        for (int k = 0; k < Dm; k++) {
            int sw = k >> 2;
            const float4* pe = (const float4*)(sEinT + k * SEIN);
            float4 ea = pe[(ebk * 2) ^ sw];
            float4 eb = pe[(ebk * 2 + 1) ^ sw];
            const ulonglong2* pw = (const ulonglong2*)(sW1 + k * Hm + jb * 8);
            ulonglong2 wA = pw[0], wB = pw[1];
            float ev[8] = {ea.x, ea.y, ea.z, ea.w, eb.x, eb.y, eb.z, eb.w};
#pragma unroll
            for (int i = 0; i < 8; i++) {
                uint64_t ed = pack2(ev[i], ev[i]);
                acc[i][0] = ffma2(ed, wA.x, acc[i][0]);
                acc[i][1] = ffma2(ed, wA.y, acc[i][1]);
                acc[i][2] = ffma2(ed, wB.x, acc[i][2]);
                acc[i][3] = ffma2(ed, wB.y, acc[i][3]);
            }
        }
        __syncthreads();                  // sEinT dead; overlay sHT

        // ---- relu + store H^T [64][128], quad swizzle q ^ jb ----
#pragma unroll
        for (int jj = 0; jj < 8; jj++) {
            int j = jb * 8 + jj;
            float f[8];
#pragma unroll
            for (int i = 0; i < 8; i++) {
                float2 v = unpack2(acc[i][jj >> 1]);
                f[i] = fmaxf((jj & 1) ? v.y : v.x, 0.f);
            }
            *(float4*)(sHT + j * 128 + (((ebk * 2)     ^ jb) << 2)) = make_float4(f[0], f[1], f[2], f[3]);
            *(float4*)(sHT + j * 128 + (((ebk * 2 + 1) ^ jb) << 2)) = make_float4(f[4], f[5], f[6], f[7]);
        }
        __syncthreads();

        // ---- GEMM2: OUT[128x32] = relu(H) @ W2 + b2 (weights from smem) ----
        uint64_t out[8][2];
        {
            ulonglong2 bb = *(const ulonglong2*)(sB2 + jb * 4);
#pragma unroll
            for (int i = 0; i < 8; i++) { out[i][0] = bb.x; out[i][1] = bb.y; }
        }
#pragma unroll 4
        for (int k = 0; k < Hm; k++) {
            int sw = (k >> 3) & 7;
            const float4* ph = (const float4*)(sHT + k * 128);
            float4 h0 = ph[(ebk * 2) ^ sw];
            float4 h1 = ph[(ebk * 2 + 1) ^ sw];
            ulonglong2 w = *(const ulonglong2*)(sW2 + k * Dm + jb * 4);
            float hv[8] = {h0.x, h0.y, h0.z, h0.w, h1.x, h1.y, h1.z, h1.w};
#pragma unroll
            for (int i = 0; i < 8; i++) {
                uint64_t hd = pack2(hv[i], hv[i]);
                out[i][0] = ffma2(hd, w.x, out[i][0]);
                out[i][1] = ffma2(hd, w.y, out[i][1]);
            }
        }
        // ---- epilogue: write e (fp32 last layer / fp16 else) + RED agg ----
#pragma unroll
        for (int i = 0; i < 8; i++) {
            int eL = ebk * 8 + i, eg = e0 + eL;
            if (eg < E) {
                float2 a = unpack2(out[i][0]); float2 b = unpack2(out[i][1]);
                if (eoutf) {
                    *(float4*)(eoutf + (size_t)eg * Dm + jb * 4) = make_float4(a.x, a.y, b.x, b.y);
                } else {
                    uint2 st;
                    ((__half2*)&st)[0] = __floats2half2_rn(a.x, a.y);
                    ((__half2*)&st)[1] = __floats2half2_rn(b.x, b.y);
                    *(uint2*)(g_e16 + (size_t)eg * Dm + jb * 4) = st;
                }
                red_add_v4(g_agg + (size_t)sD[eL] * Dm + jb * 4, a.x, a.y, b.x, b.y);
            }
        }
    }
}

// ---------------- per-layer: node MLP — 128-thread tiles + fused xg RED ------
__global__ void __launch_bounds__(128, 4) k_node(
    float* __restrict__ x, const int* __restrict__ batch,
    const float* __restrict__ W1, const float* __restrict__ W2, const float* __restrict__ b2,
    int N)
{
    extern __shared__ float smem[];
    float* sIn = smem;     // [64][132]: rows 0..31 = x^T, rows 32..63 = (agg*rd)^T
    float* sHT = smem;     // overlay after GEMM1: [64][128]
    __shared__ int sBt[TEB];
    int t = threadIdx.x;
    int n0 = blockIdx.x * TEB;
    sBt[t] = batch[min(n0 + t, N - 1)];
    {
        int l8 = t & 7, g8 = t >> 3, k0 = l8 * 4;
#pragma unroll 2
        for (int p = 0; p < 8; p++) {
            int nL = p * 16 + g8;
            int ngl = min(n0 + nL, N - 1);
            float4 vx = __ldg((const float4*)(x + (size_t)ngl * Dm) + l8);
            float rd = g_rdeg[ngl];
            float4 va = __ldg((const float4*)(g_agg + (size_t)ngl * Dm) + l8);
            int col = (((nL >> 2) ^ l8) << 2) + (nL & 3);
            sIn[(k0 + 0) * SXT + col] = vx.x;
            sIn[(k0 + 1) * SXT + col] = vx.y;
            sIn[(k0 + 2) * SXT + col] = vx.z;
            sIn[(k0 + 3) * SXT + col] = vx.w;
            sIn[(Dm + k0 + 0) * SXT + col] = va.x * rd;
            sIn[(Dm + k0 + 1) * SXT + col] = va.y * rd;
            sIn[(Dm + k0 + 2) * SXT + col] = va.z * rd;
            sIn[(Dm + k0 + 3) * SXT + col] = va.w * rd;
        }
    }
    __syncthreads();

    // ---- GEMM1: H[128x64] = In^T @ W1(rows 0..63) + hUn[batch] ----
    int jb = t & 7, nbk = t >> 3;
    uint64_t acc[8][4];
#pragma unroll
    for (int i = 0; i < 8; i++) {
        int bb = sBt[nbk * 8 + i];
        const ulonglong2* pb = (const ulonglong2*)(g_hUn + bb * Hm + jb * 8);
        ulonglong2 b0 = __ldg(pb), b1 = __ldg(pb + 1);
        acc[i][0] = b0.x; acc[i][1] = b0.y; acc[i][2] = b1.x; acc[i][3] = b1.y;
    }
#pragma unroll 4
    for (int k = 0; k < 2 * Dm; k++) {
        int sw = (k >> 2) & 7;
        const float4* pe = (const float4*)(sIn + k * SXT);
        float4 ea = pe[(nbk * 2) ^ sw];
        float4 eb = pe[(nbk * 2 + 1) ^ sw];
        ulonglong2 wA = __ldg((const ulonglong2*)(W1 + k * Hm + jb * 8));
        ulonglong2 wB = __ldg((const ulonglong2*)(W1 + k * Hm + jb * 8 + 4));
        float ev[8] = {ea.x, ea.y, ea.z, ea.w, eb.x, eb.y, eb.z, eb.w};
#pragma unroll
        for (int i = 0; i < 8; i++) {
            uint64_t ed = pack2(ev[i], ev[i]);
            acc[i][0] = ffma2(ed, wA.x, acc[i][0]);
            acc[i][1] = ffma2(ed, wA.y, acc[i][1]);
            acc[i][2] = ffma2(ed, wB.x, acc[i][2]);
            acc[i][3] = ffma2(ed, wB.y, acc[i][3]);
        }
    }
    __syncthreads();   // all reads of sIn complete before HT overlay

#pragma unroll
    for (int jj = 0; jj < 8; jj++) {
        int j = jb * 8 + jj;
        float f[8];
#pragma unroll
        for (int i = 0; i < 8; i++) {
            float2 v = unpack2(acc[i][jj >> 1]);
            f[i] = fmaxf((jj & 1) ? v.y : v.x, 0.f);
        }
        *(float4*)(sHT + j * 128 + (((nbk * 2)     ^ jb) << 2)) = make_float4(f[0], f[1], f[2], f[3]);
        *(float4*)(sHT + j * 128 + (((nbk * 2 + 1) ^ jb) << 2)) = make_float4(f[4], f[5], f[6], f[7]);
    }
    __syncthreads();

    // ---- GEMM2: OUT[128x32] = relu(H) @ W2 + b2 ----
    uint64_t out[8][2];
    {
        ulonglong2 bb = __ldg((const ulonglong2*)(b2 + jb * 4));
#pragma unroll
        for (int i = 0; i < 8; i++) { out[i][0] = bb.x; out[i][1] = bb.y; }
    }
#pragma unroll 4
    for (int k = 0; k < Hm; k++) {
        int sw = (k >> 3) & 7;
        const float4* ph = (const float4*)(sHT + k * 128);
        float4 h0 = ph[(nbk * 2) ^ sw];
        float4 h1 = ph[(nbk * 2 + 1) ^ sw];
        ulonglong2 w = __ldg((const ulonglong2*)(W2 + k * Dm + jb * 4));
        float hv[8] = {h0.x, h0.y, h0.z, h0.w, h1.x, h1.y, h1.z, h1.w};
#pragma unroll
        for (int i = 0; i < 8; i++) {
            uint64_t hd = pack2(hv[i], hv[i]);
            out[i][0] = ffma2(hd, w.x, out[i][0]);
            out[i][1] = ffma2(hd, w.y, out[i][1]);
        }
    }
    // ---- epilogue: write x + run-length-grouped RED into g_xg ----
    {
        float4 s = make_float4(0.f, 0.f, 0.f, 0.f);
        int curb = -1;
#pragma unroll
        for (int i = 0; i < 8; i++) {
            int n = n0 + nbk * 8 + i;
            if (n < N) {
                float2 a = unpack2(out[i][0]); float2 b = unpack2(out[i][1]);
                *(float4*)(x + (size_t)n * Dm + jb * 4) = make_float4(a.x, a.y, b.x, b.y);
                int bb = sBt[nbk * 8 + i];
                if (bb != curb) {
                    if (curb >= 0) red_add_v4(g_xg + curb * Dm + jb * 4, s.x, s.y, s.z, s.w);
                    curb = bb; s = make_float4(0.f, 0.f, 0.f, 0.f);
                }
                s.x += a.x; s.y += a.y; s.z += b.x; s.w += b.y;
            }
        }
        if (curb >= 0) red_add_v4(g_xg + curb * Dm + jb * 4, s.x, s.y, s.z, s.w);
    }
}

// ---------------- per-layer: global MLP + next-layer hU/hUn ------------------
static __device__ __forceinline__ int lowerb(const int* __restrict__ a, int n, int v) {
    int lo = 0, hi = n;
    while (lo < hi) { int m = (lo + hi) >> 1; if (a[m] < v) lo = m + 1; else hi = m; }
    return lo;
}
__global__ void k_glob(float* __restrict__ u, const int* __restrict__ batch,
                       const float* __restrict__ W1, const float* __restrict__ b1,
                       const float* __restrict__ W2, const float* __restrict__ b2,
                       const float* __restrict__ eW1n, const float* __restrict__ eb1n,
                       const float* __restrict__ nW1n, const float* __restrict__ nb1n,
                       int N) {
    int b = blockIdx.x, t = threadIdx.x;       // 128 threads
    __shared__ int sLo, sHi;
    __shared__ float su[2 * Dm];
    __shared__ float sh[Hm];
    __shared__ float sUn[Dm];
    if (t == 0) { sLo = lowerb(batch, N, b); sHi = lowerb(batch, N, b + 1); }
    __syncthreads();
    float cnt = fmaxf((float)(sHi - sLo), 1.0f);
    if (t < Dm) su[t] = u[b * Dm + t];
    else if (t < 2 * Dm) su[t] = g_xg[b * Dm + (t - Dm)] / cnt;
    __syncthreads();
    if (t < Hm) {
        float h = b1[t];
#pragma unroll 4
        for (int k = 0; k < 2 * Dm; k++) h += su[k] * W1[k * Hm + t];
        sh[t] = fmaxf(h, 0.f);
    }
    __syncthreads();
    if (t < Dm) {
        float o = b2[t];
#pragma unroll 4
        for (int k = 0; k < Hm; k++) o += sh[k] * W2[k * Dm + t];
        u[b * Dm + t] = o;
        sUn[t] = o;
    }
    __syncthreads();
    if (eW1n && t < Hm) {                     // next layer's hU/hUn for this batch
        float hu = eb1n[t], hun = nb1n[t];
#pragma unroll 4
        for (int k = 0; k < Dm; k++) {
            float uv = sUn[k];
            hu  += uv * eW1n[(3 * Dm + k) * Hm + t];
            hun += uv * nW1n[(2 * Dm + k) * Hm + t];
        }
        g_hU [b * Hm + t] = hu;
        g_hUn[b * Hm + t] = hun;
    }
}

// ---------------- launch -----------------------------------------------------
extern "C" void kernel_launch(void* const* d_in, const int* in_sizes, int n_in,
                              void* d_out, int out_size) {
    const float* node_feats = (const float*)d_in[0];
    const int*   edge_index = (const int*)  d_in[1];
    const float* edge_feats = (const float*)d_in[2];
    const float* glob_feats = (const float*)d_in[3];
    const int*   batch      = (const int*)  d_in[4];
    const float* ngam = (const float*)d_in[5];
    const float* nbet = (const float*)d_in[6];
    const float* egam = (const float*)d_in[7];
    const float* ebet = (const float*)d_in[8];
    const float* ggam = (const float*)d_in[9];
    const float* gbet = (const float*)d_in[10];
    const float* eW1 = (const float*)d_in[11];
    const float* eb1 = (const float*)d_in[12];
    const float* eW2 = (const float*)d_in[13];
    const float* eb2 = (const float*)d_in[14];
    const float* nW1 = (const float*)d_in[15];
    const float* nb1 = (const float*)d_in[16];
    const float* nW2 = (const float*)d_in[17];
    const float* nb2 = (const float*)d_in[18];
    const float* gW1 = (const float*)d_in[19];
    const float* gb1 = (const float*)d_in[20];
    const float* gW2 = (const float*)d_in[21];
    const float* gb2 = (const float*)d_in[22];

    const int N = in_sizes[0] / Dm;
    const int E = in_sizes[2] / Dm;
    const int B = in_sizes[3] / Dm;

    float* x = (float*)d_out;
    float* e = x + (size_t)N * Dm;
    float* u = e + (size_t)E * Dm;
    const int* src = edge_index;
    const int* dst = edge_index + E;

    const int TB = 256;
    int XB = (N * 8 + TB - 1) / TB;
    int gE = (E + TB - 1) / TB;
    int gN128 = (N + TEB - 1) / TEB;
    int nTiles = (E + TEB - 1) / TEB;
    int gEdge = nTiles < 592 ? nTiles : 592;   // 4 blocks/SM x 148 SMs

    cudaFuncSetAttribute(k_edge, cudaFuncAttributeMaxDynamicSharedMemorySize, SMEM_EDGE_BYTES);
    cudaFuncSetAttribute(k_node, cudaFuncAttributeMaxDynamicSharedMemorySize, SMEM_NODE_BYTES);

    // launch 0: BN(x,u) + zero deg
    k_bn_xu<<<XB + 1, TB>>>((const float4*)node_feats, (const float4*)glob_feats,
                            (float4*)x, (float4*)u, ngam, nbet, ggam, gbet, N, B, XB);
    // launch 1: deg count + layer-0 hU
    k_deg_hu<<<gE + 1, TB>>>(dst, u, eW1, eb1, nW1, nb1, ebet, E, B);

    for (int l = 0; l < 3; l++) {
        const float* eW1l = eW1 + (size_t)l * 4 * Dm * Hm;   // (128,64)
        const float* nW1l = nW1 + (size_t)l * 3 * Dm * Hm;   // (96,64)
        const float* gW1l = gW1 + (size_t)l * 2 * Dm * Hm;   // (64,64)
        k_pre<<<gN128, TEB>>>(x, batch, eW1l, N);            // launch 2 (l=0)
        k_edge<<<gEdge, TEB, SMEM_EDGE_BYTES>>>(src, dst,    // launch 3 (l=0) — profiled
                           (l == 0) ? edge_feats : (const float*)nullptr,   // fp32 in (l0) / g_e16
                           (l == 2) ? e : (float*)nullptr,                  // fp32 out (l2) / g_e16
                           eW1l + 2 * Dm * Hm,               // rows 64..95 (e part)
                           eW2 + (size_t)l * Hm * Dm, eb2 + l * Dm,
                           (l == 0) ? egam : (const float*)nullptr, E, nTiles);
        k_node<<<gN128, TEB, SMEM_NODE_BYTES>>>(x, batch, nW1l,
                           nW2 + (size_t)l * Hm * Dm, nb2 + l * Dm, N);
        const float* eW1n = (l < 2) ? eW1 + (size_t)(l + 1) * 4 * Dm * Hm : (const float*)nullptr;
        const float* nW1n = (l < 2) ? nW1 + (size_t)(l + 1) * 3 * Dm * Hm : (const float*)nullptr;
        k_glob<<<B, 128>>>(u, batch, gW1l, gb1 + l * Hm,
                           gW2 + (size_t)l * Hm * Dm, gb2 + l * Dm,
                           eW1n, (l < 2) ? eb1 + (l + 1) * Hm : (const float*)nullptr,
                           nW1n, (l < 2) ? nb1 + (l + 1) * Hm : (const float*)nullptr, N);
    }
}